// round 12
// baseline (speedup 1.0000x reference)
#include <cuda_runtime.h>
#include <cuda_bf16.h>
#include <cstdint>

// ---------------- problem constants ----------------
#define NTOK    4096
#define CDIM    256
#define NH      8
#define HD      32
#define LK      32
#define GB      16
#define NW      64
#define BW      1024
#define MROWS   65536
#define NKEY    48

typedef unsigned long long u64;
typedef __nv_bfloat16 bf16;

// ---------------- device-global scratch ----------------
__device__ __align__(16) bf16  g_qhi[(size_t)BW * NH * NW * HD];
__device__ __align__(16) bf16  g_qlo[(size_t)BW * NH * NW * HD];
__device__ __align__(16) bf16  g_khi[(size_t)BW * NH * NW * HD];
__device__ __align__(16) bf16  g_klo[(size_t)BW * NH * NW * HD];
__device__ __align__(16) bf16  g_vhi[(size_t)BW * NH * NW * HD];
__device__ __align__(16) bf16  g_vlo[(size_t)BW * NH * NW * HD];
__device__ __align__(16) bf16  g_xhi[(size_t)MROWS * CDIM];
__device__ __align__(16) bf16  g_xlo[(size_t)MROWS * CDIM];
__device__ __align__(16) bf16  g_aohi[(size_t)MROWS * CDIM];
__device__ __align__(16) bf16  g_aolo[(size_t)MROWS * CDIM];
__device__ __align__(16) bf16  g_wqkvT_hi[768 * 256];
__device__ __align__(16) bf16  g_wqkvT_lo[768 * 256];
__device__ __align__(16) bf16  g_wpT_hi[256 * 256];
__device__ __align__(16) bf16  g_wpT_lo[256 * 256];
__device__ __align__(16) bf16  g_ekThi[LK * NW];   // E_k^T [l][n]
__device__ __align__(16) bf16  g_ekTlo[LK * NW];
__device__ __align__(16) bf16  g_evThi[LK * NW];
__device__ __align__(16) bf16  g_evTlo[LK * NW];

// ---------------- helpers ----------------
__device__ __forceinline__ uint32_t smem_u32(const void* p) {
    uint32_t a;
    asm("{ .reg .u64 t; cvta.to.shared.u64 t, %1; cvt.u32.u64 %0, t; }" : "=r"(a) : "l"(p));
    return a;
}
__device__ __forceinline__ void cp16(uint32_t saddr, const void* gaddr) {
    asm volatile("cp.async.cg.shared.global [%0], [%1], 16;"
                 :: "r"(saddr), "l"(gaddr));
}
#define CP_COMMIT() asm volatile("cp.async.commit_group;" ::: "memory")
#define CP_WAIT(n)  asm volatile("cp.async.wait_group %0;" :: "n"(n) : "memory")

__device__ __forceinline__ void ldsm4(uint32_t (&r)[4], uint32_t addr) {
    asm volatile("ldmatrix.sync.aligned.m8n8.x4.shared.b16 {%0,%1,%2,%3}, [%4];"
                 : "=r"(r[0]), "=r"(r[1]), "=r"(r[2]), "=r"(r[3]) : "r"(addr));
}
__device__ __forceinline__ void ldsm4t(uint32_t (&r)[4], uint32_t addr) {
    asm volatile("ldmatrix.sync.aligned.m8n8.x4.trans.shared.b16 {%0,%1,%2,%3}, [%4];"
                 : "=r"(r[0]), "=r"(r[1]), "=r"(r[2]), "=r"(r[3]) : "r"(addr));
}
__device__ __forceinline__ void mma16816(float (&d)[4], const uint32_t (&a)[4],
                                         uint32_t b0, uint32_t b1) {
    asm volatile("mma.sync.aligned.m16n8k16.row.col.f32.bf16.bf16.f32 "
                 "{%0,%1,%2,%3}, {%4,%5,%6,%7}, {%8,%9}, {%0,%1,%2,%3};"
                 : "+f"(d[0]), "+f"(d[1]), "+f"(d[2]), "+f"(d[3])
                 : "r"(a[0]), "r"(a[1]), "r"(a[2]), "r"(a[3]), "r"(b0), "r"(b1));
}
__device__ __forceinline__ void mma3(float (&d)[4], const uint32_t (&ah)[4],
                                     const uint32_t (&al)[4],
                                     uint32_t bh0, uint32_t bh1,
                                     uint32_t bl0, uint32_t bl1) {
    mma16816(d, ah, bh0, bh1);
    mma16816(d, ah, bl0, bl1);
    mma16816(d, al, bh0, bh1);
}
__device__ __forceinline__ void split2(float x, float y, uint32_t& hi, uint32_t& lo) {
    __nv_bfloat162 h = __floats2bfloat162_rn(x, y);
    float rx = x - __bfloat162float(h.x);
    float ry = y - __bfloat162float(h.y);
    __nv_bfloat162 l = __floats2bfloat162_rn(rx, ry);
    hi = *(uint32_t*)&h;
    lo = *(uint32_t*)&l;
}

// =================================================================================
// conv_x: fp32 x -> window-gathered bf16 hi/lo rows [row][k]
// =================================================================================
__global__ void __launch_bounds__(256) conv_x(const float* __restrict__ x)
{
    const int t   = blockIdx.x * 256 + threadIdx.x;
    const int row = t >> 5;
    const int seg = (t & 31) * 8;
    const int w   = row >> 6, tt = row & 63;
    const int b   = w >> 6,  wrem = w & 63;
    const int gtok = (((wrem >> 3) * 8 + (tt >> 3)) << 6) + ((wrem & 7) * 8 + (tt & 7));
    const float* src = x + ((size_t)(b * NTOK + gtok)) * CDIM + seg;

    float v[8];
    *(float4*)(v)     = *(const float4*)(src);
    *(float4*)(v + 4) = *(const float4*)(src + 4);

    bf16 hs[8], ls[8];
    #pragma unroll
    for (int i = 0; i < 8; i++) {
        hs[i] = __float2bfloat16_rn(v[i]);
        ls[i] = __float2bfloat16_rn(v[i] - __bfloat162float(hs[i]));
    }
    *(uint4*)(g_xhi + (size_t)row * CDIM + seg) = *(uint4*)hs;
    *(uint4*)(g_xlo + (size_t)row * CDIM + seg) = *(uint4*)ls;
}

// =================================================================================
// conv_w: transpose + split W_qkv and W_proj into [n][k] hi/lo
// =================================================================================
__global__ void __launch_bounds__(64) conv_w(const float* __restrict__ Wqkv,
                                             const float* __restrict__ Wp)
{
    const int n = blockIdx.x;
    for (int k = threadIdx.x; k < CDIM; k += 64) {
        float val; bf16 *dh, *dl;
        if (n < 768) {
            val = Wqkv[(size_t)k * 768 + n];
            dh = g_wqkvT_hi + (size_t)n * CDIM + k;
            dl = g_wqkvT_lo + (size_t)n * CDIM + k;
        } else {
            const int n2 = n - 768;
            val = Wp[(size_t)k * CDIM + n2];
            dh = g_wpT_hi + (size_t)n2 * CDIM + k;
            dl = g_wpT_lo + (size_t)n2 * CDIM + k;
        }
        bf16 h = __float2bfloat16_rn(val);
        *dh = h;
        *dl = __float2bfloat16_rn(val - __bfloat162float(h));
    }
}

// =================================================================================
// conv_eT: E_k/E_v [64][32] -> E^T [32][64] bf16 hi/lo
// =================================================================================
__global__ void __launch_bounds__(128) conv_eT(const float* __restrict__ Ek,
                                               const float* __restrict__ Ev)
{
    const int t = blockIdx.x * 128 + threadIdx.x;   // 0..2047
    const int l = t >> 6, n = t & 63;
    float vk = Ek[n * LK + l];
    float vv = Ev[n * LK + l];
    bf16 hk = __float2bfloat16_rn(vk);
    bf16 hv = __float2bfloat16_rn(vv);
    g_ekThi[t] = hk;
    g_ekTlo[t] = __float2bfloat16_rn(vk - __bfloat162float(hk));
    g_evThi[t] = hv;
    g_evTlo[t] = __float2bfloat16_rn(vv - __bfloat162float(hv));
}

// =================================================================================
// HMMA bf16-split GEMM.  BM=128 BN=64 BK=32, 256 thr (8 warps, 4m x 2n),
//   warp tile 32x32. THREE-stage cp.async pipeline, ONE __syncthreads per iter:
//   loads for stage it+2 are issued after the sync (buffer (it-1)%3 drained),
//   giving ~2 compute iterations of latency cover (> DRAM 577cyc).
//   Grid (NT, 512): blockIdx.x = N-tile (fast) -> A reuse in L2.
// =================================================================================
#define RS   80
#define AHI  0
#define ALO  10240
#define BHI  20480
#define BLO  25600
#define STG  30720
#define SMEMB (3 * STG)

template<int MODE>
__global__ void __launch_bounds__(256) hmma_gemm(const float* __restrict__ bias,
                                                 float* __restrict__ outp)
{
    extern __shared__ char sm[];
    const uint32_t smb = smem_u32(sm);
    const int tid  = threadIdx.x;
    const int lane = tid & 31, wid = tid >> 5;
    const int warp_m = wid >> 1, warp_n = wid & 1;      // 4m x 2n
    const int bx = blockIdx.y;          // M-tile (slow axis)
    const int by = blockIdx.x;          // N-tile (fast axis -> A reuse in L2)

    const bf16* Ahi_g = (MODE == 0) ? g_xhi : g_aohi;
    const bf16* Alo_g = (MODE == 0) ? g_xlo : g_aolo;
    const bf16* Bhi_g = (MODE == 0) ? g_wqkvT_hi : g_wpT_hi;
    const bf16* Blo_g = (MODE == 0) ? g_wqkvT_lo : g_wpT_lo;

    const size_t a_base = (size_t)(bx * 128) * CDIM;
    const size_t b_base = (size_t)(by * 64) * CDIM;

    const uint32_t a_frag = (uint32_t)((warp_m * 32 + (lane & 15)) * RS
                                       + (lane >> 4) * 16);
    const uint32_t b_frag = (uint32_t)((warp_n * 32 + (lane & 7) + ((lane >> 4) << 3)) * RS
                                       + ((lane >> 3) & 1) * 16);

    float acc[2][4][4] = {};

    // per stage: A 1024 chunks (hi+lo) + B 512 chunks = 1536 x 16B; 6 per thread
    auto stage_load = [&](int s, int kt) {
        const uint32_t sb = smb + s * STG;
        #pragma unroll
        for (int i = 0; i < 6; i++) {
            const int idx = tid + i * 256;          // 0..1535
            if (idx < 1024) {
                const int hl  = idx >> 9;
                const int row = (idx >> 2) & 127;
                const int kc  = idx & 3;
                const uint32_t so = (uint32_t)((hl ? ALO : AHI) + row * RS + kc * 16);
                const bf16* src = (hl ? Alo_g : Ahi_g) + a_base
                                + (size_t)row * CDIM + (size_t)kt * 32 + kc * 8;
                cp16(sb + so, src);
            } else {
                const int j   = idx - 1024;
                const int hl  = j >> 8;
                const int row = (j >> 2) & 63;
                const int kc  = j & 3;
                const uint32_t so = (uint32_t)((hl ? BLO : BHI) + row * RS + kc * 16);
                const bf16* src = (hl ? Blo_g : Bhi_g) + b_base
                                + (size_t)row * CDIM + (size_t)kt * 32 + kc * 8;
                cp16(sb + so, src);
            }
        }
    };

    stage_load(0, 0);
    CP_COMMIT();
    stage_load(1, 1);
    CP_COMMIT();

    #pragma unroll 1
    for (int it = 0; it < 8; it++) {
        if (it < 7) CP_WAIT(1); else CP_WAIT(0);
        __syncthreads();
        if (it < 6) { stage_load((it + 2) % 3, it + 2); CP_COMMIT(); }

        const uint32_t st = smb + (it % 3) * STG;
        #pragma unroll
        for (int kk = 0; kk < 2; kk++) {
            uint32_t ahi[2][4], alo[2][4], bhi[4][2], blo[4][2];
            #pragma unroll
            for (int mt = 0; mt < 2; mt++) {
                ldsm4(ahi[mt], st + AHI + a_frag + mt * (16 * RS) + kk * 32);
                ldsm4(alo[mt], st + ALO + a_frag + mt * (16 * RS) + kk * 32);
            }
            #pragma unroll
            for (int np = 0; np < 2; np++) {
                uint32_t th[4], tl[4];
                ldsm4(th, st + BHI + b_frag + np * (16 * RS) + kk * 32);
                ldsm4(tl, st + BLO + b_frag + np * (16 * RS) + kk * 32);
                bhi[np * 2][0] = th[0]; bhi[np * 2][1] = th[1];
                bhi[np * 2 + 1][0] = th[2]; bhi[np * 2 + 1][1] = th[3];
                blo[np * 2][0] = tl[0]; blo[np * 2][1] = tl[1];
                blo[np * 2 + 1][0] = tl[2]; blo[np * 2 + 1][1] = tl[3];
            }
            #pragma unroll
            for (int mt = 0; mt < 2; mt++)
                #pragma unroll
                for (int nt = 0; nt < 4; nt++)
                    mma3(acc[mt][nt], ahi[mt], alo[mt],
                         bhi[nt][0], bhi[nt][1], blo[nt][0], blo[nt][1]);
        }
    }

    // ---------------- epilogue ----------------
    const int qrow = lane >> 2;
    const int qcol = (lane & 3) * 2;

    if (MODE == 0) {
        const int s  = by >> 2;                       // 0=q,1=k,2=v
        bf16* dhi = (s == 0) ? g_qhi : ((s == 1) ? g_khi : g_vhi);
        bf16* dlo = (s == 0) ? g_qlo : ((s == 1) ? g_klo : g_vlo);
        const float qs = (s == 0) ? 0.17677669529663687f : 1.0f;
        const int h = (by & 3) * 2 + warp_n;          // warp = one head
        #pragma unroll
        for (int nt = 0; nt < 4; nt++) {
            const int d  = nt * 8 + qcol;
            const int jg = by * 64 + warp_n * 32 + d;
            const float2 b2 = *(const float2*)(bias + jg);
            #pragma unroll
            for (int mt = 0; mt < 2; mt++) {
                #pragma unroll
                for (int half = 0; half < 2; half++) {
                    const int gr = bx * 128 + warp_m * 32 + mt * 16 + qrow + half * 8;
                    const int w  = gr >> 6, t = gr & 63;
                    const size_t hb = ((size_t)(w * NH + h)) << 11;
                    uint32_t hw, lw;
                    split2((acc[mt][nt][half * 2]     + b2.x) * qs,
                           (acc[mt][nt][half * 2 + 1] + b2.y) * qs, hw, lw);
                    *(uint32_t*)(dhi + hb + ((size_t)t << 5) + d) = hw;
                    *(uint32_t*)(dlo + hb + ((size_t)t << 5) + d) = lw;
                }
            }
        }
    } else {
        #pragma unroll
        for (int nt = 0; nt < 4; nt++) {
            const int jg = by * 64 + warp_n * 32 + nt * 8 + qcol;
            const float2 b2 = *(const float2*)(bias + jg);
            #pragma unroll
            for (int mt = 0; mt < 2; mt++) {
                #pragma unroll
                for (int half = 0; half < 2; half++) {
                    const int gr = bx * 128 + warp_m * 32 + mt * 16 + qrow + half * 8;
                    const int w  = gr >> 6, t = gr & 63;
                    const int b  = w >> 6, wrem = w & 63;
                    const int gtok = (((wrem >> 3) * 8 + (t >> 3)) << 6)
                                   + ((wrem & 7) * 8 + (t & 7));
                    float2 o = make_float2(acc[mt][nt][half * 2]     + b2.x,
                                           acc[mt][nt][half * 2 + 1] + b2.y);
                    *(float2*)(outp + ((size_t)(b * NTOK + gtok)) * CDIM + jg) = o;
                }
            }
        }
    }
}

// =================================================================================
// HMMA attention: block = (window, 2 heads), 64 threads, warp = head.
//   All per-warp buffers use 80B row stride (16B-aligned, conflict-free ldmatrix).
// =================================================================================
#define ET_SZ   4608                 // 32 rows * 144B (row = 128B data + pad)
#define ARS     80                   // attn row stride
#define W_STGH  0                    // [64][80B] hi
#define W_STGL  5120                 // [64][80B] lo
#define W_KCH   10240                // [48][80B]
#define W_KCL   14080
#define W_VCH   17920
#define W_VCL   21760
#define W_SZ    25600
#define ATTN_SM (4 * ET_SZ + 2 * W_SZ)   // 18432 + 51200 = 69632

__global__ void __launch_bounds__(64) attn_kernel(const float* __restrict__ k_bank,
                                                  const float* __restrict__ v_bank)
{
    extern __shared__ char sm[];
    const uint32_t smb = smem_u32(sm);
    const int tid  = threadIdx.x;
    const int lane = tid & 31, wid = tid >> 5;
    const int blk  = blockIdx.x;
    const int w    = blk >> 2;
    const int h    = (blk & 3) * 2 + wid;

    // ---- stage E^T matrices (block cooperative): 4 mats x 256 uint4
    {
        const bf16* srcs[4] = { g_ekThi, g_ekTlo, g_evThi, g_evTlo };
        #pragma unroll
        for (int i = 0; i < 16; i++) {
            const int idx = tid + i * 64;           // 0..1023
            const int mat = idx >> 8;
            const int r   = (idx & 255) >> 3;
            const int c   = idx & 7;
            *(uint4*)(sm + mat * ET_SZ + r * 144 + c * 16) =
                *(const uint4*)(srcs[mat] + r * 64 + c * 8);
        }
    }
    __syncthreads();

    char* wbp = sm + 4 * ET_SZ + wid * W_SZ;
    const uint32_t wbu    = smb + 4 * ET_SZ + wid * W_SZ;
    const uint32_t stg_hi = wbu + W_STGH;
    const uint32_t stg_lo = wbu + W_STGL;
    const uint32_t kc_hi  = wbu + W_KCH, kc_lo = wbu + W_KCL;
    const uint32_t vc_hi  = wbu + W_VCH, vc_lo = wbu + W_VCL;

    const size_t qkvoff = ((size_t)(w * NH + h)) << 11;    // *2048 elems
    const int r  = lane >> 2;
    const int c2 = (lane & 3) * 2;

    // ================= compression: K then V =================
    #pragma unroll 1
    for (int sel = 0; sel < 2; sel++) {
        const bf16* shi = sel ? g_vhi : g_khi;
        const bf16* slo = sel ? g_vlo : g_klo;
        const float* bank = sel ? v_bank : k_bank;
        char* ccp_hi = wbp + (sel ? W_VCH : W_KCH);
        char* ccp_lo = wbp + (sel ? W_VCL : W_KCL);
        const uint32_t ehi = smb + (sel ? 2 : 0) * ET_SZ;
        const uint32_t elo = smb + (sel ? 3 : 1) * ET_SZ;

        // stage raw tile [64][32] bf16 hi/lo (80B rows)
        #pragma unroll
        for (int i = 0; i < 8; i++) {
            const int idx = lane + i * 32;          // 0..255 (16B chunks)
            const int rr = idx >> 2, cc = idx & 3;
            *(uint4*)(wbp + W_STGH + rr * ARS + cc * 16) =
                *(const uint4*)(shi + qkvoff + idx * 8);
            *(uint4*)(wbp + W_STGL + rr * ARS + cc * 16) =
                *(const uint4*)(slo + qkvoff + idx * 8);
        }
        // bank rows -> compressed rows 32..47
        {
            const int g  = lane >> 1;
            const int d0 = (lane & 1) * 16;
            float bv[16];
            #pragma unroll
            for (int i = 0; i < 4; i++)
                *(float4*)(bv + i * 4) =
                    *(const float4*)(bank + g * CDIM + h * HD + d0 + i * 4);
            #pragma unroll
            for (int i = 0; i < 8; i++) {
                uint32_t hi, lo;
                split2(bv[2 * i], bv[2 * i + 1], hi, lo);
                *(uint32_t*)(ccp_hi + (32 + g) * ARS + (d0 + 2 * i) * 2) = hi;
                *(uint32_t*)(ccp_lo + (32 + g) * ARS + (d0 + 2 * i) * 2) = lo;
            }
        }
        __syncwarp();

        // Kc = E^T @ K : M=32(l) N=32(d) K=64(t)
        float acc[2][4][4] = {};
        #pragma unroll
        for (int kt = 0; kt < 4; kt++) {
            uint32_t Ah[2][4], Al[2][4], Bh[2][4], Bl[2][4];
            #pragma unroll
            for (int mt = 0; mt < 2; mt++) {
                const uint32_t ao = (uint32_t)((mt * 16 + (lane & 15)) * 144
                                               + kt * 32 + (lane >> 4) * 16);
                ldsm4(Ah[mt], ehi + ao);
                ldsm4(Al[mt], elo + ao);
            }
            const uint32_t to = (uint32_t)((kt * 16 + (lane & 7) + ((lane >> 3) & 1) * 8) * ARS
                                           + (lane >> 4) * 16);
            #pragma unroll
            for (int dg = 0; dg < 2; dg++) {
                ldsm4t(Bh[dg], stg_hi + to + dg * 32);
                ldsm4t(Bl[dg], stg_lo + to + dg * 32);
            }
            #pragma unroll
            for (int mt = 0; mt < 2; mt++)
                #pragma unroll
                for (int dg = 0; dg < 2; dg++) {
                    mma3(acc[mt][dg * 2],     Ah[mt], Al[mt],
                         Bh[dg][0], Bh[dg][1], Bl[dg][0], Bl[dg][1]);
                    mma3(acc[mt][dg * 2 + 1], Ah[mt], Al[mt],
                         Bh[dg][2], Bh[dg][3], Bl[dg][2], Bl[dg][3]);
                }
        }
        // store compressed rows 0..31
        #pragma unroll
        for (int mt = 0; mt < 2; mt++)
            #pragma unroll
            for (int nt = 0; nt < 4; nt++) {
                const int d = nt * 8 + c2;
                uint32_t h0, l0, h1, l1;
                split2(acc[mt][nt][0], acc[mt][nt][1], h0, l0);
                split2(acc[mt][nt][2], acc[mt][nt][3], h1, l1);
                *(uint32_t*)(ccp_hi + (mt * 16 + r) * ARS + d * 2)     = h0;
                *(uint32_t*)(ccp_lo + (mt * 16 + r) * ARS + d * 2)     = l0;
                *(uint32_t*)(ccp_hi + (mt * 16 + r + 8) * ARS + d * 2) = h1;
                *(uint32_t*)(ccp_lo + (mt * 16 + r + 8) * ARS + d * 2) = l1;
            }
        __syncwarp();
    }

    // ================= stage Q (pre-scaled in qkv epilogue) =================
    #pragma unroll
    for (int i = 0; i < 8; i++) {
        const int idx = lane + i * 32;
        const int rr = idx >> 2, cc = idx & 3;
        *(uint4*)(wbp + W_STGH + rr * ARS + cc * 16) =
            *(const uint4*)(g_qhi + qkvoff + idx * 8);
        *(uint4*)(wbp + W_STGL + rr * ARS + cc * 16) =
            *(const uint4*)(g_qlo + qkvoff + idx * 8);
    }
    __syncwarp();

    // ================= QK: M=64 N=48 K=32 =================
    float S[4][6][4] = {};
    #pragma unroll
    for (int kd = 0; kd < 2; kd++) {
        uint32_t Qh[4][4], Ql[4][4], Kh[3][4], Kl[3][4];
        #pragma unroll
        for (int mt = 0; mt < 4; mt++) {
            const uint32_t ao = (uint32_t)((mt * 16 + (lane & 15)) * ARS
                                           + kd * 32 + (lane >> 4) * 16);
            ldsm4(Qh[mt], stg_hi + ao);
            ldsm4(Ql[mt], stg_lo + ao);
        }
        const uint32_t bo = (uint32_t)(((lane & 7) + ((lane >> 4) << 3)) * ARS
                                       + ((lane >> 3) & 1) * 16 + kd * 32);
        #pragma unroll
        for (int jg = 0; jg < 3; jg++) {
            ldsm4(Kh[jg], kc_hi + jg * (16 * ARS) + bo);
            ldsm4(Kl[jg], kc_lo + jg * (16 * ARS) + bo);
        }
        #pragma unroll
        for (int mt = 0; mt < 4; mt++)
            #pragma unroll
            for (int jg = 0; jg < 3; jg++) {
                mma3(S[mt][jg * 2],     Qh[mt], Ql[mt],
                     Kh[jg][0], Kh[jg][1], Kl[jg][0], Kl[jg][1]);
                mma3(S[mt][jg * 2 + 1], Qh[mt], Ql[mt],
                     Kh[jg][2], Kh[jg][3], Kl[jg][2], Kl[jg][3]);
            }
    }

    // ================= softmax (no max subtraction; scores O(1)) =================
    float invA[4], invB[4];
    #pragma unroll
    for (int mt = 0; mt < 4; mt++) {
        float sA = 0.f, sB = 0.f;
        #pragma unroll
        for (int nt = 0; nt < 6; nt++) {
            S[mt][nt][0] = __expf(S[mt][nt][0]);
            S[mt][nt][1] = __expf(S[mt][nt][1]);
            S[mt][nt][2] = __expf(S[mt][nt][2]);
            S[mt][nt][3] = __expf(S[mt][nt][3]);
            sA += S[mt][nt][0] + S[mt][nt][1];
            sB += S[mt][nt][2] + S[mt][nt][3];
        }
        sA += __shfl_xor_sync(0xFFFFFFFFu, sA, 1);
        sA += __shfl_xor_sync(0xFFFFFFFFu, sA, 2);
        sB += __shfl_xor_sync(0xFFFFFFFFu, sB, 1);
        sB += __shfl_xor_sync(0xFFFFFFFFu, sB, 2);
        invA[mt] = 1.f / sA;
        invB[mt] = 1.f / sB;
    }

    // ================= PV: M=64 N=32 K=48 =================
    float O[4][4][4] = {};
    #pragma unroll
    for (int jg = 0; jg < 3; jg++) {
        uint32_t Ph[4][4], Pl[4][4];
        #pragma unroll
        for (int mt = 0; mt < 4; mt++) {
            split2(S[mt][2 * jg][0],     S[mt][2 * jg][1],     Ph[mt][0], Pl[mt][0]);
            split2(S[mt][2 * jg][2],     S[mt][2 * jg][3],     Ph[mt][1], Pl[mt][1]);
            split2(S[mt][2 * jg + 1][0], S[mt][2 * jg + 1][1], Ph[mt][2], Pl[mt][2]);
            split2(S[mt][2 * jg + 1][2], S[mt][2 * jg + 1][3], Ph[mt][3], Pl[mt][3]);
        }
        uint32_t Vh[2][4], Vl[2][4];
        const uint32_t vo = (uint32_t)((jg * 16 + (lane & 7) + ((lane >> 3) & 1) * 8) * ARS
                                       + (lane >> 4) * 16);
        #pragma unroll
        for (int dg = 0; dg < 2; dg++) {
            ldsm4t(Vh[dg], vc_hi + vo + dg * 32);
            ldsm4t(Vl[dg], vc_lo + vo + dg * 32);
        }
        #pragma unroll
        for (int mt = 0; mt < 4; mt++)
            #pragma unroll
            for (int dg = 0; dg < 2; dg++) {
                mma3(O[mt][dg * 2],     Ph[mt], Pl[mt],
                     Vh[dg][0], Vh[dg][1], Vl[dg][0], Vl[dg][1]);
                mma3(O[mt][dg * 2 + 1], Ph[mt], Pl[mt],
                     Vh[dg][2], Vh[dg][3], Vl[dg][2], Vl[dg][3]);
            }
    }

    // ================= normalize + out via smem restage (144B rows) =================
    __syncwarp();
    #pragma unroll
    for (int mt = 0; mt < 4; mt++)
        #pragma unroll
        for (int nt = 0; nt < 4; nt++) {
            const int cc = nt * 8 + c2;
            *(float2*)(wbp + (mt * 16 + r) * 144 + cc * 4) =
                make_float2(O[mt][nt][0] * invA[mt], O[mt][nt][1] * invA[mt]);
            *(float2*)(wbp + (mt * 16 + r + 8) * 144 + cc * 4) =
                make_float2(O[mt][nt][2] * invB[mt], O[mt][nt][3] * invB[mt]);
        }
    __syncwarp();
    #pragma unroll
    for (int rr = 0; rr < 2; rr++) {
        const int r2 = lane + rr * 32;
        float v[32];
        #pragma unroll
        for (int i = 0; i < 8; i++)
            *(float4*)(v + i * 4) = *(const float4*)(wbp + r2 * 144 + i * 16);
        uint32_t hw[16], lw[16];
        #pragma unroll
        for (int i = 0; i < 16; i++)
            split2(v[2 * i], v[2 * i + 1], hw[i], lw[i]);
        const size_t off = ((size_t)(w * NW + r2)) * CDIM + h * HD;
        #pragma unroll
        for (int i = 0; i < 4; i++) {
            *(uint4*)(g_aohi + off + i * 8) = *(uint4*)(hw + i * 4);
            *(uint4*)(g_aolo + off + i * 8) = *(uint4*)(lw + i * 4);
        }
    }
}

// =================================================================================
extern "C" void kernel_launch(void* const* d_in, const int* in_sizes, int n_in,
                              void* d_out, int out_size)
{
    (void)in_sizes; (void)n_in; (void)out_size;
    const float* x     = (const float*)d_in[0];
    const float* Wqkv  = (const float*)d_in[1];
    const float* bqkv  = (const float*)d_in[2];
    const float* E_k   = (const float*)d_in[3];
    const float* E_v   = (const float*)d_in[4];
    const float* kbank = (const float*)d_in[5];
    const float* vbank = (const float*)d_in[6];
    const float* Wp    = (const float*)d_in[7];
    const float* bp    = (const float*)d_in[8];
    float* out = (float*)d_out;

    cudaFuncSetAttribute(hmma_gemm<0>,
                         cudaFuncAttributeMaxDynamicSharedMemorySize, SMEMB);
    cudaFuncSetAttribute(hmma_gemm<1>,
                         cudaFuncAttributeMaxDynamicSharedMemorySize, SMEMB);
    cudaFuncSetAttribute(attn_kernel,
                         cudaFuncAttributeMaxDynamicSharedMemorySize, ATTN_SM);

    conv_x<<<8192, 256>>>(x);
    conv_w<<<1024, 64>>>(Wqkv, Wp);
    conv_eT<<<16, 128>>>(E_k, E_v);
    hmma_gemm<0><<<dim3(12, 512), 256, SMEMB>>>(bqkv, nullptr);
    attn_kernel<<<BW * 4, 64, ATTN_SM>>>(kbank, vbank);
    hmma_gemm<1><<<dim3(4, 512), 256, SMEMB>>>(bp, out);
}

// round 13
// speedup vs baseline: 1.3297x; 1.3297x over previous
#include <cuda_runtime.h>
#include <cuda_bf16.h>
#include <cuda_fp16.h>
#include <cstdint>

// ---------------- problem constants ----------------
#define NTOK    4096
#define CDIM    256
#define NH      8
#define HD      32
#define LK      32
#define GB      16
#define NW      64
#define BW      1024
#define MROWS   65536
#define NKEY    48

typedef unsigned long long u64;
typedef __nv_bfloat16 bf16;
typedef __half fp16;

// ---------------- device-global scratch ----------------
__device__ __align__(16) bf16  g_qhi[(size_t)BW * NH * NW * HD];
__device__ __align__(16) bf16  g_qlo[(size_t)BW * NH * NW * HD];
__device__ __align__(16) bf16  g_khi[(size_t)BW * NH * NW * HD];
__device__ __align__(16) bf16  g_klo[(size_t)BW * NH * NW * HD];
__device__ __align__(16) bf16  g_vhi[(size_t)BW * NH * NW * HD];
__device__ __align__(16) bf16  g_vlo[(size_t)BW * NH * NW * HD];
__device__ __align__(16) fp16  g_xhi[(size_t)MROWS * CDIM];
__device__ __align__(16) fp16  g_xlo[(size_t)MROWS * CDIM];
__device__ __align__(16) fp16  g_aohi[(size_t)MROWS * CDIM];
__device__ __align__(16) fp16  g_aolo[(size_t)MROWS * CDIM];
__device__ __align__(16) fp16  g_wqkvT[768 * 256];     // single fp16 (B side)
__device__ __align__(16) fp16  g_wpT[256 * 256];
__device__ __align__(16) bf16  g_ekThi[LK * NW];       // E_k^T [l][n] (attn, bf16)
__device__ __align__(16) bf16  g_ekTlo[LK * NW];
__device__ __align__(16) bf16  g_evThi[LK * NW];
__device__ __align__(16) bf16  g_evTlo[LK * NW];

// ---------------- helpers ----------------
__device__ __forceinline__ uint32_t smem_u32(const void* p) {
    uint32_t a;
    asm("{ .reg .u64 t; cvta.to.shared.u64 t, %1; cvt.u32.u64 %0, t; }" : "=r"(a) : "l"(p));
    return a;
}
__device__ __forceinline__ void cp16(uint32_t saddr, const void* gaddr) {
    asm volatile("cp.async.cg.shared.global [%0], [%1], 16;"
                 :: "r"(saddr), "l"(gaddr));
}
#define CP_COMMIT() asm volatile("cp.async.commit_group;" ::: "memory")
#define CP_WAIT(n)  asm volatile("cp.async.wait_group %0;" :: "n"(n) : "memory")

__device__ __forceinline__ void ldsm4(uint32_t (&r)[4], uint32_t addr) {
    asm volatile("ldmatrix.sync.aligned.m8n8.x4.shared.b16 {%0,%1,%2,%3}, [%4];"
                 : "=r"(r[0]), "=r"(r[1]), "=r"(r[2]), "=r"(r[3]) : "r"(addr));
}
__device__ __forceinline__ void ldsm4t(uint32_t (&r)[4], uint32_t addr) {
    asm volatile("ldmatrix.sync.aligned.m8n8.x4.trans.shared.b16 {%0,%1,%2,%3}, [%4];"
                 : "=r"(r[0]), "=r"(r[1]), "=r"(r[2]), "=r"(r[3]) : "r"(addr));
}
// bf16 mma (attention)
__device__ __forceinline__ void mma16816(float (&d)[4], const uint32_t (&a)[4],
                                         uint32_t b0, uint32_t b1) {
    asm volatile("mma.sync.aligned.m16n8k16.row.col.f32.bf16.bf16.f32 "
                 "{%0,%1,%2,%3}, {%4,%5,%6,%7}, {%8,%9}, {%0,%1,%2,%3};"
                 : "+f"(d[0]), "+f"(d[1]), "+f"(d[2]), "+f"(d[3])
                 : "r"(a[0]), "r"(a[1]), "r"(a[2]), "r"(a[3]), "r"(b0), "r"(b1));
}
// fp16 mma (GEMMs)
__device__ __forceinline__ void mma16816h(float (&d)[4], const uint32_t (&a)[4],
                                          uint32_t b0, uint32_t b1) {
    asm volatile("mma.sync.aligned.m16n8k16.row.col.f32.f16.f16.f32 "
                 "{%0,%1,%2,%3}, {%4,%5,%6,%7}, {%8,%9}, {%0,%1,%2,%3};"
                 : "+f"(d[0]), "+f"(d[1]), "+f"(d[2]), "+f"(d[3])
                 : "r"(a[0]), "r"(a[1]), "r"(a[2]), "r"(a[3]), "r"(b0), "r"(b1));
}
__device__ __forceinline__ void mma3(float (&d)[4], const uint32_t (&ah)[4],
                                     const uint32_t (&al)[4],
                                     uint32_t bh0, uint32_t bh1,
                                     uint32_t bl0, uint32_t bl1) {
    mma16816(d, ah, bh0, bh1);
    mma16816(d, ah, bl0, bl1);
    mma16816(d, al, bh0, bh1);
}
// bf16 split (attn / qkv epilogue)
__device__ __forceinline__ void split2(float x, float y, uint32_t& hi, uint32_t& lo) {
    __nv_bfloat162 h = __floats2bfloat162_rn(x, y);
    float rx = x - __bfloat162float(h.x);
    float ry = y - __bfloat162float(h.y);
    __nv_bfloat162 l = __floats2bfloat162_rn(rx, ry);
    hi = *(uint32_t*)&h;
    lo = *(uint32_t*)&l;
}
// fp16 split (GEMM A-side)
__device__ __forceinline__ void split2h(float x, float y, uint32_t& hi, uint32_t& lo) {
    __half2 h = __floats2half2_rn(x, y);
    float rx = x - __half2float(h.x);
    float ry = y - __half2float(h.y);
    __half2 l = __floats2half2_rn(rx, ry);
    hi = *(uint32_t*)&h;
    lo = *(uint32_t*)&l;
}

// =================================================================================
// conv_x: fp32 x -> window-gathered fp16 hi/lo rows [row][k]
// =================================================================================
__global__ void __launch_bounds__(256) conv_x(const float* __restrict__ x)
{
    const int t   = blockIdx.x * 256 + threadIdx.x;
    const int row = t >> 5;
    const int seg = (t & 31) * 8;
    const int w   = row >> 6, tt = row & 63;
    const int b   = w >> 6,  wrem = w & 63;
    const int gtok = (((wrem >> 3) * 8 + (tt >> 3)) << 6) + ((wrem & 7) * 8 + (tt & 7));
    const float* src = x + ((size_t)(b * NTOK + gtok)) * CDIM + seg;

    float v[8];
    *(float4*)(v)     = *(const float4*)(src);
    *(float4*)(v + 4) = *(const float4*)(src + 4);

    uint32_t hw[4], lw[4];
    #pragma unroll
    for (int i = 0; i < 4; i++)
        split2h(v[2 * i], v[2 * i + 1], hw[i], lw[i]);
    *(uint4*)(g_xhi + (size_t)row * CDIM + seg) = *(uint4*)hw;
    *(uint4*)(g_xlo + (size_t)row * CDIM + seg) = *(uint4*)lw;
}

// =================================================================================
// conv_w: transpose W_qkv and W_proj into [n][k] single fp16
// =================================================================================
__global__ void __launch_bounds__(64) conv_w(const float* __restrict__ Wqkv,
                                             const float* __restrict__ Wp)
{
    const int n = blockIdx.x;
    for (int k = threadIdx.x; k < CDIM; k += 64) {
        if (n < 768) {
            g_wqkvT[(size_t)n * CDIM + k] = __float2half_rn(Wqkv[(size_t)k * 768 + n]);
        } else {
            const int n2 = n - 768;
            g_wpT[(size_t)n2 * CDIM + k] = __float2half_rn(Wp[(size_t)k * CDIM + n2]);
        }
    }
}

// =================================================================================
// conv_eT: E_k/E_v [64][32] -> E^T [32][64] bf16 hi/lo (attn internal)
// =================================================================================
__global__ void __launch_bounds__(128) conv_eT(const float* __restrict__ Ek,
                                               const float* __restrict__ Ev)
{
    const int t = blockIdx.x * 128 + threadIdx.x;   // 0..2047
    const int l = t >> 6, n = t & 63;
    float vk = Ek[n * LK + l];
    float vv = Ev[n * LK + l];
    bf16 hk = __float2bfloat16_rn(vk);
    bf16 hv = __float2bfloat16_rn(vv);
    g_ekThi[t] = hk;
    g_ekTlo[t] = __float2bfloat16_rn(vk - __bfloat162float(hk));
    g_evThi[t] = hv;
    g_evTlo[t] = __float2bfloat16_rn(vv - __bfloat162float(hv));
}

// =================================================================================
// HMMA fp16 GEMM, A split (hi+lo), B single fp16 -> 2 mmas per tile.
//   BM=128 BN=128 BK=32, 256 thr, warp tile 64x32 (2m x 4n), 2-stage cp.async.
//   Grid (NT, 512): blockIdx.x = N-tile (fast axis) -> A reuse in L2.
//   MODE 0: qkv -> writes q/k/v as bf16 hi/lo (q pre-scaled by 1/sqrt(hd))
//   MODE 1: proj -> window-reverse fp32 out + bias
// =================================================================================
#define RS   80
#define AHI  0
#define ALO  10240
#define BB   20480
#define STG  30720
#define SMEMB (2 * STG)

template<int MODE>
__global__ void __launch_bounds__(256) hmma_gemm(const float* __restrict__ bias,
                                                 float* __restrict__ outp)
{
    extern __shared__ char sm[];
    const uint32_t smb = smem_u32(sm);
    const int tid  = threadIdx.x;
    const int lane = tid & 31, wid = tid >> 5;
    const int warp_m = wid >> 2, warp_n = wid & 3;      // 2m x 4n
    const int bx = blockIdx.y;          // M-tile (slow axis)
    const int by = blockIdx.x;          // N-tile (fast axis)

    const fp16* Ahi_g = (MODE == 0) ? g_xhi : g_aohi;
    const fp16* Alo_g = (MODE == 0) ? g_xlo : g_aolo;
    const fp16* B_g   = (MODE == 0) ? g_wqkvT : g_wpT;

    const size_t a_base = (size_t)(bx * 128) * CDIM;
    const size_t b_base = (size_t)(by * 128) * CDIM;

    const uint32_t a_frag = (uint32_t)((warp_m * 64 + (lane & 15)) * RS
                                       + (lane >> 4) * 16);
    const uint32_t b_frag = (uint32_t)((warp_n * 32 + (lane & 7) + ((lane >> 4) << 3)) * RS
                                       + ((lane >> 3) & 1) * 16);

    float acc[4][4][4] = {};

    // per stage: A 1024 chunks (hi+lo) + B 512 chunks = 1536 x 16B; 6 per thread
    auto stage_load = [&](int s, int kt) {
        const uint32_t sb = smb + s * STG;
        #pragma unroll
        for (int i = 0; i < 6; i++) {
            const int idx = tid + i * 256;          // 0..1535
            if (idx < 1024) {
                const int hl  = idx >> 9;
                const int row = (idx >> 2) & 127;
                const int kc  = idx & 3;
                const uint32_t so = (uint32_t)((hl ? ALO : AHI) + row * RS + kc * 16);
                const fp16* src = (hl ? Alo_g : Ahi_g) + a_base
                                + (size_t)row * CDIM + (size_t)kt * 32 + kc * 8;
                cp16(sb + so, src);
            } else {
                const int j   = idx - 1024;
                const int row = j >> 2;
                const int kc  = j & 3;
                const uint32_t so = (uint32_t)(BB + row * RS + kc * 16);
                const fp16* src = B_g + b_base
                                + (size_t)row * CDIM + (size_t)kt * 32 + kc * 8;
                cp16(sb + so, src);
            }
        }
    };

    stage_load(0, 0);
    CP_COMMIT();

    #pragma unroll 1
    for (int it = 0; it < 8; it++) {
        if (it < 7) { stage_load((it + 1) & 1, it + 1); CP_COMMIT(); CP_WAIT(1); }
        else        { CP_WAIT(0); }
        __syncthreads();

        const uint32_t st = smb + (it & 1) * STG;
        #pragma unroll
        for (int kk = 0; kk < 2; kk++) {
            uint32_t ahi[4][4], alo[4][4], bb[4][2];
            #pragma unroll
            for (int mt = 0; mt < 4; mt++) {
                ldsm4(ahi[mt], st + AHI + a_frag + mt * (16 * RS) + kk * 32);
                ldsm4(alo[mt], st + ALO + a_frag + mt * (16 * RS) + kk * 32);
            }
            #pragma unroll
            for (int np = 0; np < 2; np++) {
                uint32_t tb[4];
                ldsm4(tb, st + BB + b_frag + np * (16 * RS) + kk * 32);
                bb[np * 2][0] = tb[0]; bb[np * 2][1] = tb[1];
                bb[np * 2 + 1][0] = tb[2]; bb[np * 2 + 1][1] = tb[3];
            }
            #pragma unroll
            for (int mt = 0; mt < 4; mt++)
                #pragma unroll
                for (int nt = 0; nt < 4; nt++) {
                    mma16816h(acc[mt][nt], ahi[mt], bb[nt][0], bb[nt][1]);
                    mma16816h(acc[mt][nt], alo[mt], bb[nt][0], bb[nt][1]);
                }
        }
        __syncthreads();
    }

    // ---------------- epilogue ----------------
    const int w = bx * 2 + warp_m;
    const int qrow = lane >> 2;
    const int qcol = (lane & 3) * 2;

    if (MODE == 0) {
        const int s  = by >> 1;                       // 0=q,1=k,2=v
        bf16* dhi = (s == 0) ? g_qhi : ((s == 1) ? g_khi : g_vhi);
        bf16* dlo = (s == 0) ? g_qlo : ((s == 1) ? g_klo : g_vlo);
        const float qs = (s == 0) ? 0.17677669529663687f : 1.0f;
        const int h = (by & 1) * 4 + warp_n;
        const size_t hb = ((size_t)(w * NH + h)) << 11;
        #pragma unroll
        for (int nt = 0; nt < 4; nt++) {
            const int d  = nt * 8 + qcol;
            const int jg = by * 128 + warp_n * 32 + d;
            const float2 b2 = *(const float2*)(bias + jg);
            #pragma unroll
            for (int mt = 0; mt < 4; mt++) {
                const int tok = mt * 16 + qrow;
                uint32_t h0, l0, h1, l1;
                split2((acc[mt][nt][0] + b2.x) * qs, (acc[mt][nt][1] + b2.y) * qs, h0, l0);
                split2((acc[mt][nt][2] + b2.x) * qs, (acc[mt][nt][3] + b2.y) * qs, h1, l1);
                *(uint32_t*)(dhi + hb + ((size_t)tok << 5) + d)       = h0;
                *(uint32_t*)(dlo + hb + ((size_t)tok << 5) + d)       = l0;
                *(uint32_t*)(dhi + hb + ((size_t)(tok + 8) << 5) + d) = h1;
                *(uint32_t*)(dlo + hb + ((size_t)(tok + 8) << 5) + d) = l1;
            }
        }
    } else {
        const int b = w >> 6, wrem = w & 63;
        #pragma unroll
        for (int nt = 0; nt < 4; nt++) {
            const int jg = by * 128 + warp_n * 32 + nt * 8 + qcol;
            const float2 b2 = *(const float2*)(bias + jg);
            #pragma unroll
            for (int mt = 0; mt < 4; mt++) {
                #pragma unroll
                for (int half = 0; half < 2; half++) {
                    const int tok = mt * 16 + qrow + half * 8;
                    const int gtok = (((wrem >> 3) * 8 + (tok >> 3)) << 6)
                                   + ((wrem & 7) * 8 + (tok & 7));
                    float2 o = make_float2(acc[mt][nt][half * 2]     + b2.x,
                                           acc[mt][nt][half * 2 + 1] + b2.y);
                    *(float2*)(outp + ((size_t)(b * NTOK + gtok)) * CDIM + jg) = o;
                }
            }
        }
    }
}

// =================================================================================
// HMMA attention: block = (window, 2 heads), 64 threads, warp = head.
//   Internally bf16 3-mma (proven); output written as fp16 hi/lo for proj.
// =================================================================================
#define ET_SZ   4608                 // 32 rows * 144B
#define ARS     80                   // attn row stride
#define W_STGH  0
#define W_STGL  5120
#define W_KCH   10240
#define W_KCL   14080
#define W_VCH   17920
#define W_VCL   21760
#define W_SZ    25600
#define ATTN_SM (4 * ET_SZ + 2 * W_SZ)   // 69632

__global__ void __launch_bounds__(64) attn_kernel(const float* __restrict__ k_bank,
                                                  const float* __restrict__ v_bank)
{
    extern __shared__ char sm[];
    const uint32_t smb = smem_u32(sm);
    const int tid  = threadIdx.x;
    const int lane = tid & 31, wid = tid >> 5;
    const int blk  = blockIdx.x;
    const int w    = blk >> 2;
    const int h    = (blk & 3) * 2 + wid;

    // ---- stage E^T matrices (block cooperative): 4 mats x 256 uint4
    {
        const bf16* srcs[4] = { g_ekThi, g_ekTlo, g_evThi, g_evTlo };
        #pragma unroll
        for (int i = 0; i < 16; i++) {
            const int idx = tid + i * 64;
            const int mat = idx >> 8;
            const int r   = (idx & 255) >> 3;
            const int c   = idx & 7;
            *(uint4*)(sm + mat * ET_SZ + r * 144 + c * 16) =
                *(const uint4*)(srcs[mat] + r * 64 + c * 8);
        }
    }
    __syncthreads();

    char* wbp = sm + 4 * ET_SZ + wid * W_SZ;
    const uint32_t wbu    = smb + 4 * ET_SZ + wid * W_SZ;
    const uint32_t stg_hi = wbu + W_STGH;
    const uint32_t stg_lo = wbu + W_STGL;
    const uint32_t kc_hi  = wbu + W_KCH, kc_lo = wbu + W_KCL;
    const uint32_t vc_hi  = wbu + W_VCH, vc_lo = wbu + W_VCL;

    const size_t qkvoff = ((size_t)(w * NH + h)) << 11;
    const int r  = lane >> 2;
    const int c2 = (lane & 3) * 2;

    // ================= compression: K then V =================
    #pragma unroll 1
    for (int sel = 0; sel < 2; sel++) {
        const bf16* shi = sel ? g_vhi : g_khi;
        const bf16* slo = sel ? g_vlo : g_klo;
        const float* bank = sel ? v_bank : k_bank;
        char* ccp_hi = wbp + (sel ? W_VCH : W_KCH);
        char* ccp_lo = wbp + (sel ? W_VCL : W_KCL);
        const uint32_t ehi = smb + (sel ? 2 : 0) * ET_SZ;
        const uint32_t elo = smb + (sel ? 3 : 1) * ET_SZ;

        #pragma unroll
        for (int i = 0; i < 8; i++) {
            const int idx = lane + i * 32;
            const int rr = idx >> 2, cc = idx & 3;
            *(uint4*)(wbp + W_STGH + rr * ARS + cc * 16) =
                *(const uint4*)(shi + qkvoff + idx * 8);
            *(uint4*)(wbp + W_STGL + rr * ARS + cc * 16) =
                *(const uint4*)(slo + qkvoff + idx * 8);
        }
        {
            const int g  = lane >> 1;
            const int d0 = (lane & 1) * 16;
            float bv[16];
            #pragma unroll
            for (int i = 0; i < 4; i++)
                *(float4*)(bv + i * 4) =
                    *(const float4*)(bank + g * CDIM + h * HD + d0 + i * 4);
            #pragma unroll
            for (int i = 0; i < 8; i++) {
                uint32_t hi, lo;
                split2(bv[2 * i], bv[2 * i + 1], hi, lo);
                *(uint32_t*)(ccp_hi + (32 + g) * ARS + (d0 + 2 * i) * 2) = hi;
                *(uint32_t*)(ccp_lo + (32 + g) * ARS + (d0 + 2 * i) * 2) = lo;
            }
        }
        __syncwarp();

        float acc[2][4][4] = {};
        #pragma unroll
        for (int kt = 0; kt < 4; kt++) {
            uint32_t Ah[2][4], Al[2][4], Bh[2][4], Bl[2][4];
            #pragma unroll
            for (int mt = 0; mt < 2; mt++) {
                const uint32_t ao = (uint32_t)((mt * 16 + (lane & 15)) * 144
                                               + kt * 32 + (lane >> 4) * 16);
                ldsm4(Ah[mt], ehi + ao);
                ldsm4(Al[mt], elo + ao);
            }
            const uint32_t to = (uint32_t)((kt * 16 + (lane & 7) + ((lane >> 3) & 1) * 8) * ARS
                                           + (lane >> 4) * 16);
            #pragma unroll
            for (int dg = 0; dg < 2; dg++) {
                ldsm4t(Bh[dg], stg_hi + to + dg * 32);
                ldsm4t(Bl[dg], stg_lo + to + dg * 32);
            }
            #pragma unroll
            for (int mt = 0; mt < 2; mt++)
                #pragma unroll
                for (int dg = 0; dg < 2; dg++) {
                    mma3(acc[mt][dg * 2],     Ah[mt], Al[mt],
                         Bh[dg][0], Bh[dg][1], Bl[dg][0], Bl[dg][1]);
                    mma3(acc[mt][dg * 2 + 1], Ah[mt], Al[mt],
                         Bh[dg][2], Bh[dg][3], Bl[dg][2], Bl[dg][3]);
                }
        }
        #pragma unroll
        for (int mt = 0; mt < 2; mt++)
            #pragma unroll
            for (int nt = 0; nt < 4; nt++) {
                const int d = nt * 8 + c2;
                uint32_t h0, l0, h1, l1;
                split2(acc[mt][nt][0], acc[mt][nt][1], h0, l0);
                split2(acc[mt][nt][2], acc[mt][nt][3], h1, l1);
                *(uint32_t*)(ccp_hi + (mt * 16 + r) * ARS + d * 2)     = h0;
                *(uint32_t*)(ccp_lo + (mt * 16 + r) * ARS + d * 2)     = l0;
                *(uint32_t*)(ccp_hi + (mt * 16 + r + 8) * ARS + d * 2) = h1;
                *(uint32_t*)(ccp_lo + (mt * 16 + r + 8) * ARS + d * 2) = l1;
            }
        __syncwarp();
    }

    // ================= stage Q (pre-scaled in qkv epilogue) =================
    #pragma unroll
    for (int i = 0; i < 8; i++) {
        const int idx = lane + i * 32;
        const int rr = idx >> 2, cc = idx & 3;
        *(uint4*)(wbp + W_STGH + rr * ARS + cc * 16) =
            *(const uint4*)(g_qhi + qkvoff + idx * 8);
        *(uint4*)(wbp + W_STGL + rr * ARS + cc * 16) =
            *(const uint4*)(g_qlo + qkvoff + idx * 8);
    }
    __syncwarp();

    // ================= QK: M=64 N=48 K=32 =================
    float S[4][6][4] = {};
    #pragma unroll
    for (int kd = 0; kd < 2; kd++) {
        uint32_t Qh[4][4], Ql[4][4], Kh[3][4], Kl[3][4];
        #pragma unroll
        for (int mt = 0; mt < 4; mt++) {
            const uint32_t ao = (uint32_t)((mt * 16 + (lane & 15)) * ARS
                                           + kd * 32 + (lane >> 4) * 16);
            ldsm4(Qh[mt], stg_hi + ao);
            ldsm4(Ql[mt], stg_lo + ao);
        }
        const uint32_t bo = (uint32_t)(((lane & 7) + ((lane >> 4) << 3)) * ARS
                                       + ((lane >> 3) & 1) * 16 + kd * 32);
        #pragma unroll
        for (int jg = 0; jg < 3; jg++) {
            ldsm4(Kh[jg], kc_hi + jg * (16 * ARS) + bo);
            ldsm4(Kl[jg], kc_lo + jg * (16 * ARS) + bo);
        }
        #pragma unroll
        for (int mt = 0; mt < 4; mt++)
            #pragma unroll
            for (int jg = 0; jg < 3; jg++) {
                mma3(S[mt][jg * 2],     Qh[mt], Ql[mt],
                     Kh[jg][0], Kh[jg][1], Kl[jg][0], Kl[jg][1]);
                mma3(S[mt][jg * 2 + 1], Qh[mt], Ql[mt],
                     Kh[jg][2], Kh[jg][3], Kl[jg][2], Kl[jg][3]);
            }
    }

    // ================= softmax =================
    float invA[4], invB[4];
    #pragma unroll
    for (int mt = 0; mt < 4; mt++) {
        float sA = 0.f, sB = 0.f;
        #pragma unroll
        for (int nt = 0; nt < 6; nt++) {
            S[mt][nt][0] = __expf(S[mt][nt][0]);
            S[mt][nt][1] = __expf(S[mt][nt][1]);
            S[mt][nt][2] = __expf(S[mt][nt][2]);
            S[mt][nt][3] = __expf(S[mt][nt][3]);
            sA += S[mt][nt][0] + S[mt][nt][1];
            sB += S[mt][nt][2] + S[mt][nt][3];
        }
        sA += __shfl_xor_sync(0xFFFFFFFFu, sA, 1);
        sA += __shfl_xor_sync(0xFFFFFFFFu, sA, 2);
        sB += __shfl_xor_sync(0xFFFFFFFFu, sB, 1);
        sB += __shfl_xor_sync(0xFFFFFFFFu, sB, 2);
        invA[mt] = 1.f / sA;
        invB[mt] = 1.f / sB;
    }

    // ================= PV: M=64 N=32 K=48 =================
    float O[4][4][4] = {};
    #pragma unroll
    for (int jg = 0; jg < 3; jg++) {
        uint32_t Ph[4][4], Pl[4][4];
        #pragma unroll
        for (int mt = 0; mt < 4; mt++) {
            split2(S[mt][2 * jg][0],     S[mt][2 * jg][1],     Ph[mt][0], Pl[mt][0]);
            split2(S[mt][2 * jg][2],     S[mt][2 * jg][3],     Ph[mt][1], Pl[mt][1]);
            split2(S[mt][2 * jg + 1][0], S[mt][2 * jg + 1][1], Ph[mt][2], Pl[mt][2]);
            split2(S[mt][2 * jg + 1][2], S[mt][2 * jg + 1][3], Ph[mt][3], Pl[mt][3]);
        }
        uint32_t Vh[2][4], Vl[2][4];
        const uint32_t vo = (uint32_t)((jg * 16 + (lane & 7) + ((lane >> 3) & 1) * 8) * ARS
                                       + (lane >> 4) * 16);
        #pragma unroll
        for (int dg = 0; dg < 2; dg++) {
            ldsm4t(Vh[dg], vc_hi + vo + dg * 32);
            ldsm4t(Vl[dg], vc_lo + vo + dg * 32);
        }
        #pragma unroll
        for (int mt = 0; mt < 4; mt++)
            #pragma unroll
            for (int dg = 0; dg < 2; dg++) {
                mma3(O[mt][dg * 2],     Ph[mt], Pl[mt],
                     Vh[dg][0], Vh[dg][1], Vl[dg][0], Vl[dg][1]);
                mma3(O[mt][dg * 2 + 1], Ph[mt], Pl[mt],
                     Vh[dg][2], Vh[dg][3], Vl[dg][2], Vl[dg][3]);
            }
    }

    // ================= normalize + out via smem restage (144B rows) =================
    __syncwarp();
    #pragma unroll
    for (int mt = 0; mt < 4; mt++)
        #pragma unroll
        for (int nt = 0; nt < 4; nt++) {
            const int cc = nt * 8 + c2;
            *(float2*)(wbp + (mt * 16 + r) * 144 + cc * 4) =
                make_float2(O[mt][nt][0] * invA[mt], O[mt][nt][1] * invA[mt]);
            *(float2*)(wbp + (mt * 16 + r + 8) * 144 + cc * 4) =
                make_float2(O[mt][nt][2] * invB[mt], O[mt][nt][3] * invB[mt]);
        }
    __syncwarp();
    #pragma unroll
    for (int rr = 0; rr < 2; rr++) {
        const int r2 = lane + rr * 32;
        float v[32];
        #pragma unroll
        for (int i = 0; i < 8; i++)
            *(float4*)(v + i * 4) = *(const float4*)(wbp + r2 * 144 + i * 16);
        uint32_t hw[16], lw[16];
        #pragma unroll
        for (int i = 0; i < 16; i++)
            split2h(v[2 * i], v[2 * i + 1], hw[i], lw[i]);
        const size_t off = ((size_t)(w * NW + r2)) * CDIM + h * HD;
        #pragma unroll
        for (int i = 0; i < 4; i++) {
            *(uint4*)(g_aohi + off + i * 8) = *(uint4*)(hw + i * 4);
            *(uint4*)(g_aolo + off + i * 8) = *(uint4*)(lw + i * 4);
        }
    }
}

// =================================================================================
extern "C" void kernel_launch(void* const* d_in, const int* in_sizes, int n_in,
                              void* d_out, int out_size)
{
    (void)in_sizes; (void)n_in; (void)out_size;
    const float* x     = (const float*)d_in[0];
    const float* Wqkv  = (const float*)d_in[1];
    const float* bqkv  = (const float*)d_in[2];
    const float* E_k   = (const float*)d_in[3];
    const float* E_v   = (const float*)d_in[4];
    const float* kbank = (const float*)d_in[5];
    const float* vbank = (const float*)d_in[6];
    const float* Wp    = (const float*)d_in[7];
    const float* bp    = (const float*)d_in[8];
    float* out = (float*)d_out;

    cudaFuncSetAttribute(hmma_gemm<0>,
                         cudaFuncAttributeMaxDynamicSharedMemorySize, SMEMB);
    cudaFuncSetAttribute(hmma_gemm<1>,
                         cudaFuncAttributeMaxDynamicSharedMemorySize, SMEMB);
    cudaFuncSetAttribute(attn_kernel,
                         cudaFuncAttributeMaxDynamicSharedMemorySize, ATTN_SM);

    conv_x<<<8192, 256>>>(x);
    conv_w<<<1024, 64>>>(Wqkv, Wp);
    conv_eT<<<16, 128>>>(E_k, E_v);
    hmma_gemm<0><<<dim3(6, 512), 256, SMEMB>>>(bqkv, nullptr);
    attn_kernel<<<BW * 4, 64, ATTN_SM>>>(kbank, vbank);
    hmma_gemm<1><<<dim3(2, 512), 256, SMEMB>>>(bp, out);
}

// round 14
// speedup vs baseline: 1.6658x; 1.2528x over previous
#include <cuda_runtime.h>
#include <cuda_bf16.h>
#include <cuda_fp16.h>
#include <cstdint>

// ---------------- problem constants ----------------
#define NTOK    4096
#define CDIM    256
#define NH      8
#define HD      32
#define LK      32
#define GB      16
#define NW      64
#define BW      1024
#define MROWS   65536
#define NKEY    48

typedef unsigned long long u64;
typedef __nv_bfloat16 bf16;
typedef __half fp16;

// ---------------- device-global scratch ----------------
__device__ __align__(16) bf16  g_qhi[(size_t)BW * NH * NW * HD];
__device__ __align__(16) bf16  g_qlo[(size_t)BW * NH * NW * HD];
__device__ __align__(16) bf16  g_khi[(size_t)BW * NH * NW * HD];
__device__ __align__(16) bf16  g_klo[(size_t)BW * NH * NW * HD];
__device__ __align__(16) bf16  g_vhi[(size_t)BW * NH * NW * HD];
__device__ __align__(16) bf16  g_vlo[(size_t)BW * NH * NW * HD];
__device__ __align__(16) fp16  g_x[(size_t)MROWS * CDIM];      // single fp16 A (qkv)
__device__ __align__(16) fp16  g_ao[(size_t)MROWS * CDIM];     // single fp16 A (proj)
__device__ __align__(16) fp16  g_wqkvT[768 * 256];             // single fp16 B
__device__ __align__(16) fp16  g_wpT[256 * 256];
__device__ __align__(16) bf16  g_ekThi[LK * NW];               // E_k^T [l][n] (attn)
__device__ __align__(16) bf16  g_ekTlo[LK * NW];
__device__ __align__(16) bf16  g_evThi[LK * NW];
__device__ __align__(16) bf16  g_evTlo[LK * NW];

// ---------------- helpers ----------------
__device__ __forceinline__ uint32_t smem_u32(const void* p) {
    uint32_t a;
    asm("{ .reg .u64 t; cvta.to.shared.u64 t, %1; cvt.u32.u64 %0, t; }" : "=r"(a) : "l"(p));
    return a;
}
__device__ __forceinline__ void cp16(uint32_t saddr, const void* gaddr) {
    asm volatile("cp.async.cg.shared.global [%0], [%1], 16;"
                 :: "r"(saddr), "l"(gaddr));
}
#define CP_COMMIT() asm volatile("cp.async.commit_group;" ::: "memory")
#define CP_WAIT(n)  asm volatile("cp.async.wait_group %0;" :: "n"(n) : "memory")

__device__ __forceinline__ void ldsm4(uint32_t (&r)[4], uint32_t addr) {
    asm volatile("ldmatrix.sync.aligned.m8n8.x4.shared.b16 {%0,%1,%2,%3}, [%4];"
                 : "=r"(r[0]), "=r"(r[1]), "=r"(r[2]), "=r"(r[3]) : "r"(addr));
}
__device__ __forceinline__ void ldsm4t(uint32_t (&r)[4], uint32_t addr) {
    asm volatile("ldmatrix.sync.aligned.m8n8.x4.trans.shared.b16 {%0,%1,%2,%3}, [%4];"
                 : "=r"(r[0]), "=r"(r[1]), "=r"(r[2]), "=r"(r[3]) : "r"(addr));
}
// bf16 mma (attention)
__device__ __forceinline__ void mma16816(float (&d)[4], const uint32_t (&a)[4],
                                         uint32_t b0, uint32_t b1) {
    asm volatile("mma.sync.aligned.m16n8k16.row.col.f32.bf16.bf16.f32 "
                 "{%0,%1,%2,%3}, {%4,%5,%6,%7}, {%8,%9}, {%0,%1,%2,%3};"
                 : "+f"(d[0]), "+f"(d[1]), "+f"(d[2]), "+f"(d[3])
                 : "r"(a[0]), "r"(a[1]), "r"(a[2]), "r"(a[3]), "r"(b0), "r"(b1));
}
// fp16 mma (GEMMs)
__device__ __forceinline__ void mma16816h(float (&d)[4], const uint32_t (&a)[4],
                                          uint32_t b0, uint32_t b1) {
    asm volatile("mma.sync.aligned.m16n8k16.row.col.f32.f16.f16.f32 "
                 "{%0,%1,%2,%3}, {%4,%5,%6,%7}, {%8,%9}, {%0,%1,%2,%3};"
                 : "+f"(d[0]), "+f"(d[1]), "+f"(d[2]), "+f"(d[3])
                 : "r"(a[0]), "r"(a[1]), "r"(a[2]), "r"(a[3]), "r"(b0), "r"(b1));
}
__device__ __forceinline__ void mma3(float (&d)[4], const uint32_t (&ah)[4],
                                     const uint32_t (&al)[4],
                                     uint32_t bh0, uint32_t bh1,
                                     uint32_t bl0, uint32_t bl1) {
    mma16816(d, ah, bh0, bh1);
    mma16816(d, ah, bl0, bl1);
    mma16816(d, al, bh0, bh1);
}
// bf16 split (attn / qkv epilogue)
__device__ __forceinline__ void split2(float x, float y, uint32_t& hi, uint32_t& lo) {
    __nv_bfloat162 h = __floats2bfloat162_rn(x, y);
    float rx = x - __bfloat162float(h.x);
    float ry = y - __bfloat162float(h.y);
    __nv_bfloat162 l = __floats2bfloat162_rn(rx, ry);
    hi = *(uint32_t*)&h;
    lo = *(uint32_t*)&l;
}

// =================================================================================
// conv_x: fp32 x -> window-gathered single fp16 rows [row][k]
// =================================================================================
__global__ void __launch_bounds__(256) conv_x(const float* __restrict__ x)
{
    const int t   = blockIdx.x * 256 + threadIdx.x;
    const int row = t >> 5;
    const int seg = (t & 31) * 8;
    const int w   = row >> 6, tt = row & 63;
    const int b   = w >> 6,  wrem = w & 63;
    const int gtok = (((wrem >> 3) * 8 + (tt >> 3)) << 6) + ((wrem & 7) * 8 + (tt & 7));
    const float* src = x + ((size_t)(b * NTOK + gtok)) * CDIM + seg;

    float v[8];
    *(float4*)(v)     = *(const float4*)(src);
    *(float4*)(v + 4) = *(const float4*)(src + 4);

    uint32_t hw[4];
    #pragma unroll
    for (int i = 0; i < 4; i++) {
        __half2 h = __floats2half2_rn(v[2 * i], v[2 * i + 1]);
        hw[i] = *(uint32_t*)&h;
    }
    *(uint4*)(g_x + (size_t)row * CDIM + seg) = *(uint4*)hw;
}

// =================================================================================
// conv_w: transpose W_qkv and W_proj into [n][k] single fp16
// =================================================================================
__global__ void __launch_bounds__(64) conv_w(const float* __restrict__ Wqkv,
                                             const float* __restrict__ Wp)
{
    const int n = blockIdx.x;
    for (int k = threadIdx.x; k < CDIM; k += 64) {
        if (n < 768) {
            g_wqkvT[(size_t)n * CDIM + k] = __float2half_rn(Wqkv[(size_t)k * 768 + n]);
        } else {
            const int n2 = n - 768;
            g_wpT[(size_t)n2 * CDIM + k] = __float2half_rn(Wp[(size_t)k * CDIM + n2]);
        }
    }
}

// =================================================================================
// conv_eT: E_k/E_v [64][32] -> E^T [32][64] bf16 hi/lo (attn internal)
// =================================================================================
__global__ void __launch_bounds__(128) conv_eT(const float* __restrict__ Ek,
                                               const float* __restrict__ Ev)
{
    const int t = blockIdx.x * 128 + threadIdx.x;   // 0..2047
    const int l = t >> 6, n = t & 63;
    float vk = Ek[n * LK + l];
    float vv = Ev[n * LK + l];
    bf16 hk = __float2bfloat16_rn(vk);
    bf16 hv = __float2bfloat16_rn(vv);
    g_ekThi[t] = hk;
    g_ekTlo[t] = __float2bfloat16_rn(vk - __bfloat162float(hk));
    g_evThi[t] = hv;
    g_evTlo[t] = __float2bfloat16_rn(vv - __bfloat162float(hv));
}

// =================================================================================
// HMMA fp16 GEMM, single fp16 A and B -> 1 mma per tile.
//   BM=128 BN=128 BK=32, 256 thr, warp tile 64x32 (2m x 4n), 2-stage cp.async.
//   Grid (NT, 512): blockIdx.x = N-tile (fast axis) -> A reuse in L2.
//   MODE 0: qkv -> writes q/k/v as bf16 hi/lo (q pre-scaled by 1/sqrt(hd))
//   MODE 1: proj -> window-reverse fp32 out + bias
// =================================================================================
#define RS   80
#define AA   0
#define BB   10240
#define STG  20480
#define SMEMB (2 * STG)

template<int MODE>
__global__ void __launch_bounds__(256) hmma_gemm(const float* __restrict__ bias,
                                                 float* __restrict__ outp)
{
    extern __shared__ char sm[];
    const uint32_t smb = smem_u32(sm);
    const int tid  = threadIdx.x;
    const int lane = tid & 31, wid = tid >> 5;
    const int warp_m = wid >> 2, warp_n = wid & 3;      // 2m x 4n
    const int bx = blockIdx.y;          // M-tile (slow axis)
    const int by = blockIdx.x;          // N-tile (fast axis)

    const fp16* A_g = (MODE == 0) ? g_x : g_ao;
    const fp16* B_g = (MODE == 0) ? g_wqkvT : g_wpT;

    const size_t a_base = (size_t)(bx * 128) * CDIM;
    const size_t b_base = (size_t)(by * 128) * CDIM;

    const uint32_t a_frag = (uint32_t)((warp_m * 64 + (lane & 15)) * RS
                                       + (lane >> 4) * 16);
    const uint32_t b_frag = (uint32_t)((warp_n * 32 + (lane & 7) + ((lane >> 4) << 3)) * RS
                                       + ((lane >> 3) & 1) * 16);

    float acc[4][4][4] = {};

    // per stage: A 512 chunks + B 512 chunks = 1024 x 16B; 4 per thread
    auto stage_load = [&](int s, int kt) {
        const uint32_t sb = smb + s * STG;
        #pragma unroll
        for (int i = 0; i < 4; i++) {
            const int idx = tid + i * 256;          // 0..1023
            const int row = (idx >> 2) & 127;
            const int kc  = idx & 3;
            if (idx < 512) {
                const uint32_t so = (uint32_t)(AA + row * RS + kc * 16);
                cp16(sb + so, A_g + a_base + (size_t)row * CDIM + (size_t)kt * 32 + kc * 8);
            } else {
                const uint32_t so = (uint32_t)(BB + row * RS + kc * 16);
                cp16(sb + so, B_g + b_base + (size_t)row * CDIM + (size_t)kt * 32 + kc * 8);
            }
        }
    };

    stage_load(0, 0);
    CP_COMMIT();

    #pragma unroll 1
    for (int it = 0; it < 8; it++) {
        if (it < 7) { stage_load((it + 1) & 1, it + 1); CP_COMMIT(); CP_WAIT(1); }
        else        { CP_WAIT(0); }
        __syncthreads();

        const uint32_t st = smb + (it & 1) * STG;
        #pragma unroll
        for (int kk = 0; kk < 2; kk++) {
            uint32_t aa[4][4], bb[4][2];
            #pragma unroll
            for (int mt = 0; mt < 4; mt++)
                ldsm4(aa[mt], st + AA + a_frag + mt * (16 * RS) + kk * 32);
            #pragma unroll
            for (int np = 0; np < 2; np++) {
                uint32_t tb[4];
                ldsm4(tb, st + BB + b_frag + np * (16 * RS) + kk * 32);
                bb[np * 2][0] = tb[0]; bb[np * 2][1] = tb[1];
                bb[np * 2 + 1][0] = tb[2]; bb[np * 2 + 1][1] = tb[3];
            }
            #pragma unroll
            for (int mt = 0; mt < 4; mt++)
                #pragma unroll
                for (int nt = 0; nt < 4; nt++)
                    mma16816h(acc[mt][nt], aa[mt], bb[nt][0], bb[nt][1]);
        }
        __syncthreads();
    }

    // ---------------- epilogue ----------------
    const int w = bx * 2 + warp_m;
    const int qrow = lane >> 2;
    const int qcol = (lane & 3) * 2;

    if (MODE == 0) {
        const int s  = by >> 1;                       // 0=q,1=k,2=v
        bf16* dhi = (s == 0) ? g_qhi : ((s == 1) ? g_khi : g_vhi);
        bf16* dlo = (s == 0) ? g_qlo : ((s == 1) ? g_klo : g_vlo);
        const float qs = (s == 0) ? 0.17677669529663687f : 1.0f;
        const int h = (by & 1) * 4 + warp_n;
        const size_t hb = ((size_t)(w * NH + h)) << 11;
        #pragma unroll
        for (int nt = 0; nt < 4; nt++) {
            const int d  = nt * 8 + qcol;
            const int jg = by * 128 + warp_n * 32 + d;
            const float2 b2 = *(const float2*)(bias + jg);
            #pragma unroll
            for (int mt = 0; mt < 4; mt++) {
                const int tok = mt * 16 + qrow;
                uint32_t h0, l0, h1, l1;
                split2((acc[mt][nt][0] + b2.x) * qs, (acc[mt][nt][1] + b2.y) * qs, h0, l0);
                split2((acc[mt][nt][2] + b2.x) * qs, (acc[mt][nt][3] + b2.y) * qs, h1, l1);
                *(uint32_t*)(dhi + hb + ((size_t)tok << 5) + d)       = h0;
                *(uint32_t*)(dlo + hb + ((size_t)tok << 5) + d)       = l0;
                *(uint32_t*)(dhi + hb + ((size_t)(tok + 8) << 5) + d) = h1;
                *(uint32_t*)(dlo + hb + ((size_t)(tok + 8) << 5) + d) = l1;
            }
        }
    } else {
        const int b = w >> 6, wrem = w & 63;
        #pragma unroll
        for (int nt = 0; nt < 4; nt++) {
            const int jg = by * 128 + warp_n * 32 + nt * 8 + qcol;
            const float2 b2 = *(const float2*)(bias + jg);
            #pragma unroll
            for (int mt = 0; mt < 4; mt++) {
                #pragma unroll
                for (int half = 0; half < 2; half++) {
                    const int tok = mt * 16 + qrow + half * 8;
                    const int gtok = (((wrem >> 3) * 8 + (tok >> 3)) << 6)
                                   + ((wrem & 7) * 8 + (tok & 7));
                    float2 o = make_float2(acc[mt][nt][half * 2]     + b2.x,
                                           acc[mt][nt][half * 2 + 1] + b2.y);
                    *(float2*)(outp + ((size_t)(b * NTOK + gtok)) * CDIM + jg) = o;
                }
            }
        }
    }
}

// =================================================================================
// HMMA attention: block = (window, 2 heads), 64 threads, warp = head.
//   Internally bf16 3-mma; output written as single fp16 for proj A.
// =================================================================================
#define ET_SZ   4608                 // 32 rows * 144B
#define ARS     80                   // attn row stride
#define W_STGH  0
#define W_STGL  5120
#define W_KCH   10240
#define W_KCL   14080
#define W_VCH   17920
#define W_VCL   21760
#define W_SZ    25600
#define ATTN_SM (4 * ET_SZ + 2 * W_SZ)   // 69632

__global__ void __launch_bounds__(64) attn_kernel(const float* __restrict__ k_bank,
                                                  const float* __restrict__ v_bank)
{
    extern __shared__ char sm[];
    const uint32_t smb = smem_u32(sm);
    const int tid  = threadIdx.x;
    const int lane = tid & 31, wid = tid >> 5;
    const int blk  = blockIdx.x;
    const int w    = blk >> 2;
    const int h    = (blk & 3) * 2 + wid;

    // ---- stage E^T matrices (block cooperative): 4 mats x 256 uint4
    {
        const bf16* srcs[4] = { g_ekThi, g_ekTlo, g_evThi, g_evTlo };
        #pragma unroll
        for (int i = 0; i < 16; i++) {
            const int idx = tid + i * 64;
            const int mat = idx >> 8;
            const int r   = (idx & 255) >> 3;
            const int c   = idx & 7;
            *(uint4*)(sm + mat * ET_SZ + r * 144 + c * 16) =
                *(const uint4*)(srcs[mat] + r * 64 + c * 8);
        }
    }
    __syncthreads();

    char* wbp = sm + 4 * ET_SZ + wid * W_SZ;
    const uint32_t wbu    = smb + 4 * ET_SZ + wid * W_SZ;
    const uint32_t stg_hi = wbu + W_STGH;
    const uint32_t stg_lo = wbu + W_STGL;
    const uint32_t kc_hi  = wbu + W_KCH, kc_lo = wbu + W_KCL;
    const uint32_t vc_hi  = wbu + W_VCH, vc_lo = wbu + W_VCL;

    const size_t qkvoff = ((size_t)(w * NH + h)) << 11;
    const int r  = lane >> 2;
    const int c2 = (lane & 3) * 2;

    // ================= compression: K then V =================
    #pragma unroll 1
    for (int sel = 0; sel < 2; sel++) {
        const bf16* shi = sel ? g_vhi : g_khi;
        const bf16* slo = sel ? g_vlo : g_klo;
        const float* bank = sel ? v_bank : k_bank;
        char* ccp_hi = wbp + (sel ? W_VCH : W_KCH);
        char* ccp_lo = wbp + (sel ? W_VCL : W_KCL);
        const uint32_t ehi = smb + (sel ? 2 : 0) * ET_SZ;
        const uint32_t elo = smb + (sel ? 3 : 1) * ET_SZ;

        #pragma unroll
        for (int i = 0; i < 8; i++) {
            const int idx = lane + i * 32;
            const int rr = idx >> 2, cc = idx & 3;
            *(uint4*)(wbp + W_STGH + rr * ARS + cc * 16) =
                *(const uint4*)(shi + qkvoff + idx * 8);
            *(uint4*)(wbp + W_STGL + rr * ARS + cc * 16) =
                *(const uint4*)(slo + qkvoff + idx * 8);
        }
        {
            const int g  = lane >> 1;
            const int d0 = (lane & 1) * 16;
            float bv[16];
            #pragma unroll
            for (int i = 0; i < 4; i++)
                *(float4*)(bv + i * 4) =
                    *(const float4*)(bank + g * CDIM + h * HD + d0 + i * 4);
            #pragma unroll
            for (int i = 0; i < 8; i++) {
                uint32_t hi, lo;
                split2(bv[2 * i], bv[2 * i + 1], hi, lo);
                *(uint32_t*)(ccp_hi + (32 + g) * ARS + (d0 + 2 * i) * 2) = hi;
                *(uint32_t*)(ccp_lo + (32 + g) * ARS + (d0 + 2 * i) * 2) = lo;
            }
        }
        __syncwarp();

        float acc[2][4][4] = {};
        #pragma unroll
        for (int kt = 0; kt < 4; kt++) {
            uint32_t Ah[2][4], Al[2][4], Bh[2][4], Bl[2][4];
            #pragma unroll
            for (int mt = 0; mt < 2; mt++) {
                const uint32_t ao = (uint32_t)((mt * 16 + (lane & 15)) * 144
                                               + kt * 32 + (lane >> 4) * 16);
                ldsm4(Ah[mt], ehi + ao);
                ldsm4(Al[mt], elo + ao);
            }
            const uint32_t to = (uint32_t)((kt * 16 + (lane & 7) + ((lane >> 3) & 1) * 8) * ARS
                                           + (lane >> 4) * 16);
            #pragma unroll
            for (int dg = 0; dg < 2; dg++) {
                ldsm4t(Bh[dg], stg_hi + to + dg * 32);
                ldsm4t(Bl[dg], stg_lo + to + dg * 32);
            }
            #pragma unroll
            for (int mt = 0; mt < 2; mt++)
                #pragma unroll
                for (int dg = 0; dg < 2; dg++) {
                    mma3(acc[mt][dg * 2],     Ah[mt], Al[mt],
                         Bh[dg][0], Bh[dg][1], Bl[dg][0], Bl[dg][1]);
                    mma3(acc[mt][dg * 2 + 1], Ah[mt], Al[mt],
                         Bh[dg][2], Bh[dg][3], Bl[dg][2], Bl[dg][3]);
                }
        }
        #pragma unroll
        for (int mt = 0; mt < 2; mt++)
            #pragma unroll
            for (int nt = 0; nt < 4; nt++) {
                const int d = nt * 8 + c2;
                uint32_t h0, l0, h1, l1;
                split2(acc[mt][nt][0], acc[mt][nt][1], h0, l0);
                split2(acc[mt][nt][2], acc[mt][nt][3], h1, l1);
                *(uint32_t*)(ccp_hi + (mt * 16 + r) * ARS + d * 2)     = h0;
                *(uint32_t*)(ccp_lo + (mt * 16 + r) * ARS + d * 2)     = l0;
                *(uint32_t*)(ccp_hi + (mt * 16 + r + 8) * ARS + d * 2) = h1;
                *(uint32_t*)(ccp_lo + (mt * 16 + r + 8) * ARS + d * 2) = l1;
            }
        __syncwarp();
    }

    // ================= stage Q (pre-scaled in qkv epilogue) =================
    #pragma unroll
    for (int i = 0; i < 8; i++) {
        const int idx = lane + i * 32;
        const int rr = idx >> 2, cc = idx & 3;
        *(uint4*)(wbp + W_STGH + rr * ARS + cc * 16) =
            *(const uint4*)(g_qhi + qkvoff + idx * 8);
        *(uint4*)(wbp + W_STGL + rr * ARS + cc * 16) =
            *(const uint4*)(g_qlo + qkvoff + idx * 8);
    }
    __syncwarp();

    // ================= QK: M=64 N=48 K=32 =================
    float S[4][6][4] = {};
    #pragma unroll
    for (int kd = 0; kd < 2; kd++) {
        uint32_t Qh[4][4], Ql[4][4], Kh[3][4], Kl[3][4];
        #pragma unroll
        for (int mt = 0; mt < 4; mt++) {
            const uint32_t ao = (uint32_t)((mt * 16 + (lane & 15)) * ARS
                                           + kd * 32 + (lane >> 4) * 16);
            ldsm4(Qh[mt], stg_hi + ao);
            ldsm4(Ql[mt], stg_lo + ao);
        }
        const uint32_t bo = (uint32_t)(((lane & 7) + ((lane >> 4) << 3)) * ARS
                                       + ((lane >> 3) & 1) * 16 + kd * 32);
        #pragma unroll
        for (int jg = 0; jg < 3; jg++) {
            ldsm4(Kh[jg], kc_hi + jg * (16 * ARS) + bo);
            ldsm4(Kl[jg], kc_lo + jg * (16 * ARS) + bo);
        }
        #pragma unroll
        for (int mt = 0; mt < 4; mt++)
            #pragma unroll
            for (int jg = 0; jg < 3; jg++) {
                mma3(S[mt][jg * 2],     Qh[mt], Ql[mt],
                     Kh[jg][0], Kh[jg][1], Kl[jg][0], Kl[jg][1]);
                mma3(S[mt][jg * 2 + 1], Qh[mt], Ql[mt],
                     Kh[jg][2], Kh[jg][3], Kl[jg][2], Kl[jg][3]);
            }
    }

    // ================= softmax =================
    float invA[4], invB[4];
    #pragma unroll
    for (int mt = 0; mt < 4; mt++) {
        float sA = 0.f, sB = 0.f;
        #pragma unroll
        for (int nt = 0; nt < 6; nt++) {
            S[mt][nt][0] = __expf(S[mt][nt][0]);
            S[mt][nt][1] = __expf(S[mt][nt][1]);
            S[mt][nt][2] = __expf(S[mt][nt][2]);
            S[mt][nt][3] = __expf(S[mt][nt][3]);
            sA += S[mt][nt][0] + S[mt][nt][1];
            sB += S[mt][nt][2] + S[mt][nt][3];
        }
        sA += __shfl_xor_sync(0xFFFFFFFFu, sA, 1);
        sA += __shfl_xor_sync(0xFFFFFFFFu, sA, 2);
        sB += __shfl_xor_sync(0xFFFFFFFFu, sB, 1);
        sB += __shfl_xor_sync(0xFFFFFFFFu, sB, 2);
        invA[mt] = 1.f / sA;
        invB[mt] = 1.f / sB;
    }

    // ================= PV: M=64 N=32 K=48 =================
    float O[4][4][4] = {};
    #pragma unroll
    for (int jg = 0; jg < 3; jg++) {
        uint32_t Ph[4][4], Pl[4][4];
        #pragma unroll
        for (int mt = 0; mt < 4; mt++) {
            split2(S[mt][2 * jg][0],     S[mt][2 * jg][1],     Ph[mt][0], Pl[mt][0]);
            split2(S[mt][2 * jg][2],     S[mt][2 * jg][3],     Ph[mt][1], Pl[mt][1]);
            split2(S[mt][2 * jg + 1][0], S[mt][2 * jg + 1][1], Ph[mt][2], Pl[mt][2]);
            split2(S[mt][2 * jg + 1][2], S[mt][2 * jg + 1][3], Ph[mt][3], Pl[mt][3]);
        }
        uint32_t Vh[2][4], Vl[2][4];
        const uint32_t vo = (uint32_t)((jg * 16 + (lane & 7) + ((lane >> 3) & 1) * 8) * ARS
                                       + (lane >> 4) * 16);
        #pragma unroll
        for (int dg = 0; dg < 2; dg++) {
            ldsm4t(Vh[dg], vc_hi + vo + dg * 32);
            ldsm4t(Vl[dg], vc_lo + vo + dg * 32);
        }
        #pragma unroll
        for (int mt = 0; mt < 4; mt++)
            #pragma unroll
            for (int dg = 0; dg < 2; dg++) {
                mma3(O[mt][dg * 2],     Ph[mt], Pl[mt],
                     Vh[dg][0], Vh[dg][1], Vl[dg][0], Vl[dg][1]);
                mma3(O[mt][dg * 2 + 1], Ph[mt], Pl[mt],
                     Vh[dg][2], Vh[dg][3], Vl[dg][2], Vl[dg][3]);
            }
    }

    // ================= normalize + out via smem restage (144B rows) =================
    __syncwarp();
    #pragma unroll
    for (int mt = 0; mt < 4; mt++)
        #pragma unroll
        for (int nt = 0; nt < 4; nt++) {
            const int cc = nt * 8 + c2;
            *(float2*)(wbp + (mt * 16 + r) * 144 + cc * 4) =
                make_float2(O[mt][nt][0] * invA[mt], O[mt][nt][1] * invA[mt]);
            *(float2*)(wbp + (mt * 16 + r + 8) * 144 + cc * 4) =
                make_float2(O[mt][nt][2] * invB[mt], O[mt][nt][3] * invB[mt]);
        }
    __syncwarp();
    #pragma unroll
    for (int rr = 0; rr < 2; rr++) {
        const int r2 = lane + rr * 32;
        float v[32];
        #pragma unroll
        for (int i = 0; i < 8; i++)
            *(float4*)(v + i * 4) = *(const float4*)(wbp + r2 * 144 + i * 16);
        uint32_t hw[16];
        #pragma unroll
        for (int i = 0; i < 16; i++) {
            __half2 hp = __floats2half2_rn(v[2 * i], v[2 * i + 1]);
            hw[i] = *(uint32_t*)&hp;
        }
        const size_t off = ((size_t)(w * NW + r2)) * CDIM + h * HD;
        #pragma unroll
        for (int i = 0; i < 4; i++)
            *(uint4*)(g_ao + off + i * 8) = *(uint4*)(hw + i * 4);
    }
}

// =================================================================================
extern "C" void kernel_launch(void* const* d_in, const int* in_sizes, int n_in,
                              void* d_out, int out_size)
{
    (void)in_sizes; (void)n_in; (void)out_size;
    const float* x     = (const float*)d_in[0];
    const float* Wqkv  = (const float*)d_in[1];
    const float* bqkv  = (const float*)d_in[2];
    const float* E_k   = (const float*)d_in[3];
    const float* E_v   = (const float*)d_in[4];
    const float* kbank = (const float*)d_in[5];
    const float* vbank = (const float*)d_in[6];
    const float* Wp    = (const float*)d_in[7];
    const float* bp    = (const float*)d_in[8];
    float* out = (float*)d_out;

    cudaFuncSetAttribute(hmma_gemm<0>,
                         cudaFuncAttributeMaxDynamicSharedMemorySize, SMEMB);
    cudaFuncSetAttribute(hmma_gemm<1>,
                         cudaFuncAttributeMaxDynamicSharedMemorySize, SMEMB);
    cudaFuncSetAttribute(attn_kernel,
                         cudaFuncAttributeMaxDynamicSharedMemorySize, ATTN_SM);

    conv_x<<<8192, 256>>>(x);
    conv_w<<<1024, 64>>>(Wqkv, Wp);
    conv_eT<<<16, 128>>>(E_k, E_v);
    hmma_gemm<0><<<dim3(6, 512), 256, SMEMB>>>(bqkv, nullptr);
    attn_kernel<<<BW * 4, 64, ATTN_SM>>>(kbank, vbank);
    hmma_gemm<1><<<dim3(2, 512), 256, SMEMB>>>(bp, out);
}

// round 15
// speedup vs baseline: 2.1853x; 1.3118x over previous
#include <cuda_runtime.h>
#include <cuda_bf16.h>
#include <cuda_fp16.h>
#include <cstdint>

// ---------------- problem constants ----------------
#define NTOK    4096
#define CDIM    256
#define NH      8
#define HD      32
#define LK      32
#define GB      16
#define NW      64
#define BW      1024
#define MROWS   65536
#define NKEY    48

typedef unsigned long long u64;
typedef __half fp16;

// ---------------- device-global scratch ----------------
__device__ __align__(16) fp16  g_q[(size_t)BW * NH * NW * HD];   // single fp16
__device__ __align__(16) fp16  g_k[(size_t)BW * NH * NW * HD];
__device__ __align__(16) fp16  g_v[(size_t)BW * NH * NW * HD];
__device__ __align__(16) fp16  g_x[(size_t)MROWS * CDIM];
__device__ __align__(16) fp16  g_ao[(size_t)MROWS * CDIM];
__device__ __align__(16) fp16  g_wqkvT[768 * 256];
__device__ __align__(16) fp16  g_wpT[256 * 256];
__device__ __align__(16) fp16  g_ekT[LK * NW];                   // E_k^T [l][n]
__device__ __align__(16) fp16  g_evT[LK * NW];

// ---------------- helpers ----------------
__device__ __forceinline__ uint32_t smem_u32(const void* p) {
    uint32_t a;
    asm("{ .reg .u64 t; cvta.to.shared.u64 t, %1; cvt.u32.u64 %0, t; }" : "=r"(a) : "l"(p));
    return a;
}
__device__ __forceinline__ void cp16(uint32_t saddr, const void* gaddr) {
    asm volatile("cp.async.cg.shared.global [%0], [%1], 16;"
                 :: "r"(saddr), "l"(gaddr));
}
#define CP_COMMIT() asm volatile("cp.async.commit_group;" ::: "memory")
#define CP_WAIT(n)  asm volatile("cp.async.wait_group %0;" :: "n"(n) : "memory")

__device__ __forceinline__ void ldsm4(uint32_t (&r)[4], uint32_t addr) {
    asm volatile("ldmatrix.sync.aligned.m8n8.x4.shared.b16 {%0,%1,%2,%3}, [%4];"
                 : "=r"(r[0]), "=r"(r[1]), "=r"(r[2]), "=r"(r[3]) : "r"(addr));
}
__device__ __forceinline__ void ldsm4t(uint32_t (&r)[4], uint32_t addr) {
    asm volatile("ldmatrix.sync.aligned.m8n8.x4.trans.shared.b16 {%0,%1,%2,%3}, [%4];"
                 : "=r"(r[0]), "=r"(r[1]), "=r"(r[2]), "=r"(r[3]) : "r"(addr));
}
__device__ __forceinline__ void mma16816h(float (&d)[4], const uint32_t (&a)[4],
                                          uint32_t b0, uint32_t b1) {
    asm volatile("mma.sync.aligned.m16n8k16.row.col.f32.f16.f16.f32 "
                 "{%0,%1,%2,%3}, {%4,%5,%6,%7}, {%8,%9}, {%0,%1,%2,%3};"
                 : "+f"(d[0]), "+f"(d[1]), "+f"(d[2]), "+f"(d[3])
                 : "r"(a[0]), "r"(a[1]), "r"(a[2]), "r"(a[3]), "r"(b0), "r"(b1));
}
__device__ __forceinline__ uint32_t h2pack(float x, float y) {
    __half2 h = __floats2half2_rn(x, y);
    return *(uint32_t*)&h;
}

// =================================================================================
// conv_x: fp32 x -> window-gathered single fp16 rows [row][k]
// =================================================================================
__global__ void __launch_bounds__(256) conv_x(const float* __restrict__ x)
{
    const int t   = blockIdx.x * 256 + threadIdx.x;
    const int row = t >> 5;
    const int seg = (t & 31) * 8;
    const int w   = row >> 6, tt = row & 63;
    const int b   = w >> 6,  wrem = w & 63;
    const int gtok = (((wrem >> 3) * 8 + (tt >> 3)) << 6) + ((wrem & 7) * 8 + (tt & 7));
    const float* src = x + ((size_t)(b * NTOK + gtok)) * CDIM + seg;

    float v[8];
    *(float4*)(v)     = *(const float4*)(src);
    *(float4*)(v + 4) = *(const float4*)(src + 4);

    uint32_t hw[4];
    #pragma unroll
    for (int i = 0; i < 4; i++)
        hw[i] = h2pack(v[2 * i], v[2 * i + 1]);
    *(uint4*)(g_x + (size_t)row * CDIM + seg) = *(uint4*)hw;
}

// =================================================================================
// conv_w: transpose W_qkv and W_proj into [n][k] single fp16
// =================================================================================
__global__ void __launch_bounds__(64) conv_w(const float* __restrict__ Wqkv,
                                             const float* __restrict__ Wp)
{
    const int n = blockIdx.x;
    for (int k = threadIdx.x; k < CDIM; k += 64) {
        if (n < 768) {
            g_wqkvT[(size_t)n * CDIM + k] = __float2half_rn(Wqkv[(size_t)k * 768 + n]);
        } else {
            const int n2 = n - 768;
            g_wpT[(size_t)n2 * CDIM + k] = __float2half_rn(Wp[(size_t)k * CDIM + n2]);
        }
    }
}

// =================================================================================
// conv_eT: E_k/E_v [64][32] -> E^T [32][64] single fp16
// =================================================================================
__global__ void __launch_bounds__(128) conv_eT(const float* __restrict__ Ek,
                                               const float* __restrict__ Ev)
{
    const int t = blockIdx.x * 128 + threadIdx.x;   // 0..2047
    const int l = t >> 6, n = t & 63;
    g_ekT[t] = __float2half_rn(Ek[n * LK + l]);
    g_evT[t] = __float2half_rn(Ev[n * LK + l]);
}

// =================================================================================
// HMMA fp16 GEMM, single fp16 A and B -> 1 mma per tile.
//   BM=128 BN=128 BK=32, 256 thr, warp tile 64x32 (2m x 4n), 2-stage cp.async.
//   Grid (NT, 512): blockIdx.x = N-tile (fast axis) -> A reuse in L2.
//   MODE 0: qkv -> writes q/k/v single fp16 (q pre-scaled by 1/sqrt(hd))
//   MODE 1: proj -> window-reverse fp32 out + bias
// =================================================================================
#define RS   80
#define AA   0
#define BB   10240
#define STG  20480
#define SMEMB (2 * STG)

template<int MODE>
__global__ void __launch_bounds__(256) hmma_gemm(const float* __restrict__ bias,
                                                 float* __restrict__ outp)
{
    extern __shared__ char sm[];
    const uint32_t smb = smem_u32(sm);
    const int tid  = threadIdx.x;
    const int lane = tid & 31, wid = tid >> 5;
    const int warp_m = wid >> 2, warp_n = wid & 3;      // 2m x 4n
    const int bx = blockIdx.y;
    const int by = blockIdx.x;

    const fp16* A_g = (MODE == 0) ? g_x : g_ao;
    const fp16* B_g = (MODE == 0) ? g_wqkvT : g_wpT;

    const size_t a_base = (size_t)(bx * 128) * CDIM;
    const size_t b_base = (size_t)(by * 128) * CDIM;

    const uint32_t a_frag = (uint32_t)((warp_m * 64 + (lane & 15)) * RS
                                       + (lane >> 4) * 16);
    const uint32_t b_frag = (uint32_t)((warp_n * 32 + (lane & 7) + ((lane >> 4) << 3)) * RS
                                       + ((lane >> 3) & 1) * 16);

    float acc[4][4][4] = {};

    auto stage_load = [&](int s, int kt) {
        const uint32_t sb = smb + s * STG;
        #pragma unroll
        for (int i = 0; i < 4; i++) {
            const int idx = tid + i * 256;          // 0..1023
            const int row = (idx >> 2) & 127;
            const int kc  = idx & 3;
            if (idx < 512) {
                const uint32_t so = (uint32_t)(AA + row * RS + kc * 16);
                cp16(sb + so, A_g + a_base + (size_t)row * CDIM + (size_t)kt * 32 + kc * 8);
            } else {
                const uint32_t so = (uint32_t)(BB + row * RS + kc * 16);
                cp16(sb + so, B_g + b_base + (size_t)row * CDIM + (size_t)kt * 32 + kc * 8);
            }
        }
    };

    stage_load(0, 0);
    CP_COMMIT();

    #pragma unroll 1
    for (int it = 0; it < 8; it++) {
        if (it < 7) { stage_load((it + 1) & 1, it + 1); CP_COMMIT(); CP_WAIT(1); }
        else        { CP_WAIT(0); }
        __syncthreads();

        const uint32_t st = smb + (it & 1) * STG;
        #pragma unroll
        for (int kk = 0; kk < 2; kk++) {
            uint32_t aa[4][4], bb[4][2];
            #pragma unroll
            for (int mt = 0; mt < 4; mt++)
                ldsm4(aa[mt], st + AA + a_frag + mt * (16 * RS) + kk * 32);
            #pragma unroll
            for (int np = 0; np < 2; np++) {
                uint32_t tb[4];
                ldsm4(tb, st + BB + b_frag + np * (16 * RS) + kk * 32);
                bb[np * 2][0] = tb[0]; bb[np * 2][1] = tb[1];
                bb[np * 2 + 1][0] = tb[2]; bb[np * 2 + 1][1] = tb[3];
            }
            #pragma unroll
            for (int mt = 0; mt < 4; mt++)
                #pragma unroll
                for (int nt = 0; nt < 4; nt++)
                    mma16816h(acc[mt][nt], aa[mt], bb[nt][0], bb[nt][1]);
        }
        __syncthreads();
    }

    // ---------------- epilogue ----------------
    const int w = bx * 2 + warp_m;
    const int qrow = lane >> 2;
    const int qcol = (lane & 3) * 2;

    if (MODE == 0) {
        const int s  = by >> 1;                       // 0=q,1=k,2=v
        fp16* dst = (s == 0) ? g_q : ((s == 1) ? g_k : g_v);
        const float qs = (s == 0) ? 0.17677669529663687f : 1.0f;
        const int h = (by & 1) * 4 + warp_n;
        const size_t hb = ((size_t)(w * NH + h)) << 11;
        #pragma unroll
        for (int nt = 0; nt < 4; nt++) {
            const int d  = nt * 8 + qcol;
            const int jg = by * 128 + warp_n * 32 + d;
            const float2 b2 = *(const float2*)(bias + jg);
            #pragma unroll
            for (int mt = 0; mt < 4; mt++) {
                const int tok = mt * 16 + qrow;
                *(uint32_t*)(dst + hb + ((size_t)tok << 5) + d) =
                    h2pack((acc[mt][nt][0] + b2.x) * qs, (acc[mt][nt][1] + b2.y) * qs);
                *(uint32_t*)(dst + hb + ((size_t)(tok + 8) << 5) + d) =
                    h2pack((acc[mt][nt][2] + b2.x) * qs, (acc[mt][nt][3] + b2.y) * qs);
            }
        }
    } else {
        const int b = w >> 6, wrem = w & 63;
        #pragma unroll
        for (int nt = 0; nt < 4; nt++) {
            const int jg = by * 128 + warp_n * 32 + nt * 8 + qcol;
            const float2 b2 = *(const float2*)(bias + jg);
            #pragma unroll
            for (int mt = 0; mt < 4; mt++) {
                #pragma unroll
                for (int half = 0; half < 2; half++) {
                    const int tok = mt * 16 + qrow + half * 8;
                    const int gtok = (((wrem >> 3) * 8 + (tok >> 3)) << 6)
                                   + ((wrem & 7) * 8 + (tok & 7));
                    float2 o = make_float2(acc[mt][nt][half * 2]     + b2.x,
                                           acc[mt][nt][half * 2 + 1] + b2.y);
                    *(float2*)(outp + ((size_t)(b * NTOK + gtok)) * CDIM + jg) = o;
                }
            }
        }
    }
}

// =================================================================================
// HMMA attention, all single fp16 (1 mma per tile).
//   Block = (window, 2 heads), 64 threads, warp = head. 80B row strides.
// =================================================================================
#define ET_SZ   4608                 // 32 rows * 144B
#define ARS     80
#define W_STG   0                    // [64][80B]  staging (K/V then Q)
#define W_KC    5120                 // [48][80B]
#define W_VC    8960                 // [48][80B]
#define W_SZ    12800
#define ATTN_SM (2 * ET_SZ + 2 * W_SZ)   // 9216 + 25600 = 34816

__global__ void __launch_bounds__(64) attn_kernel(const float* __restrict__ k_bank,
                                                  const float* __restrict__ v_bank)
{
    extern __shared__ char sm[];
    const uint32_t smb = smem_u32(sm);
    const int tid  = threadIdx.x;
    const int lane = tid & 31, wid = tid >> 5;
    const int blk  = blockIdx.x;
    const int w    = blk >> 2;
    const int h    = (blk & 3) * 2 + wid;

    // ---- stage E^T matrices (block cooperative): 2 mats x 256 uint4
    {
        const fp16* srcs[2] = { g_ekT, g_evT };
        #pragma unroll
        for (int i = 0; i < 8; i++) {
            const int idx = tid + i * 64;           // 0..511
            const int mat = idx >> 8;
            const int r   = (idx & 255) >> 3;
            const int c   = idx & 7;
            *(uint4*)(sm + mat * ET_SZ + r * 144 + c * 16) =
                *(const uint4*)(srcs[mat] + r * 64 + c * 8);
        }
    }
    __syncthreads();

    char* wbp = sm + 2 * ET_SZ + wid * W_SZ;
    const uint32_t wbu = smb + 2 * ET_SZ + wid * W_SZ;
    const uint32_t stg = wbu + W_STG;
    const uint32_t kc  = wbu + W_KC;
    const uint32_t vc  = wbu + W_VC;

    const size_t qkvoff = ((size_t)(w * NH + h)) << 11;
    const int r  = lane >> 2;
    const int c2 = (lane & 3) * 2;

    // ================= compression: K then V =================
    #pragma unroll 1
    for (int sel = 0; sel < 2; sel++) {
        const fp16* src = sel ? g_v : g_k;
        const float* bank = sel ? v_bank : k_bank;
        char* ccp = wbp + (sel ? W_VC : W_KC);
        const uint32_t eT = smb + (sel ? ET_SZ : 0);

        // stage raw tile [64][32] fp16 (80B rows, 64B data)
        #pragma unroll
        for (int i = 0; i < 8; i++) {
            const int idx = lane + i * 32;          // 0..255 (16B chunks)
            const int rr = idx >> 2, cc = idx & 3;
            *(uint4*)(wbp + W_STG + rr * ARS + cc * 16) =
                *(const uint4*)(src + qkvoff + idx * 8);
        }
        // bank rows -> compressed rows 32..47
        {
            const int g  = lane >> 1;
            const int d0 = (lane & 1) * 16;
            float bv[16];
            #pragma unroll
            for (int i = 0; i < 4; i++)
                *(float4*)(bv + i * 4) =
                    *(const float4*)(bank + g * CDIM + h * HD + d0 + i * 4);
            #pragma unroll
            for (int i = 0; i < 8; i++)
                *(uint32_t*)(ccp + (32 + g) * ARS + (d0 + 2 * i) * 2) =
                    h2pack(bv[2 * i], bv[2 * i + 1]);
        }
        __syncwarp();

        // Kc = E^T @ K : M=32(l) N=32(d) K=64(t)
        float acc[2][4][4] = {};
        #pragma unroll
        for (int kt = 0; kt < 4; kt++) {
            uint32_t A[2][4], B[2][4];
            #pragma unroll
            for (int mt = 0; mt < 2; mt++) {
                const uint32_t ao = (uint32_t)((mt * 16 + (lane & 15)) * 144
                                               + kt * 32 + (lane >> 4) * 16);
                ldsm4(A[mt], eT + ao);
            }
            const uint32_t to = (uint32_t)((kt * 16 + (lane & 7) + ((lane >> 3) & 1) * 8) * ARS
                                           + (lane >> 4) * 16);
            #pragma unroll
            for (int dg = 0; dg < 2; dg++)
                ldsm4t(B[dg], stg + to + dg * 32);
            #pragma unroll
            for (int mt = 0; mt < 2; mt++)
                #pragma unroll
                for (int dg = 0; dg < 2; dg++) {
                    mma16816h(acc[mt][dg * 2],     A[mt], B[dg][0], B[dg][1]);
                    mma16816h(acc[mt][dg * 2 + 1], A[mt], B[dg][2], B[dg][3]);
                }
        }
        // store compressed rows 0..31
        #pragma unroll
        for (int mt = 0; mt < 2; mt++)
            #pragma unroll
            for (int nt = 0; nt < 4; nt++) {
                const int d = nt * 8 + c2;
                *(uint32_t*)(ccp + (mt * 16 + r) * ARS + d * 2) =
                    h2pack(acc[mt][nt][0], acc[mt][nt][1]);
                *(uint32_t*)(ccp + (mt * 16 + r + 8) * ARS + d * 2) =
                    h2pack(acc[mt][nt][2], acc[mt][nt][3]);
            }
        __syncwarp();
    }

    // ================= stage Q (pre-scaled in qkv epilogue) =================
    #pragma unroll
    for (int i = 0; i < 8; i++) {
        const int idx = lane + i * 32;
        const int rr = idx >> 2, cc = idx & 3;
        *(uint4*)(wbp + W_STG + rr * ARS + cc * 16) =
            *(const uint4*)(g_q + qkvoff + idx * 8);
    }
    __syncwarp();

    // ================= QK: M=64 N=48 K=32 =================
    float S[4][6][4] = {};
    #pragma unroll
    for (int kd = 0; kd < 2; kd++) {
        uint32_t Q[4][4], K[3][4];
        #pragma unroll
        for (int mt = 0; mt < 4; mt++) {
            const uint32_t ao = (uint32_t)((mt * 16 + (lane & 15)) * ARS
                                           + kd * 32 + (lane >> 4) * 16);
            ldsm4(Q[mt], stg + ao);
        }
        const uint32_t bo = (uint32_t)(((lane & 7) + ((lane >> 4) << 3)) * ARS
                                       + ((lane >> 3) & 1) * 16 + kd * 32);
        #pragma unroll
        for (int jg = 0; jg < 3; jg++)
            ldsm4(K[jg], kc + jg * (16 * ARS) + bo);
        #pragma unroll
        for (int mt = 0; mt < 4; mt++)
            #pragma unroll
            for (int jg = 0; jg < 3; jg++) {
                mma16816h(S[mt][jg * 2],     Q[mt], K[jg][0], K[jg][1]);
                mma16816h(S[mt][jg * 2 + 1], Q[mt], K[jg][2], K[jg][3]);
            }
    }

    // ================= softmax =================
    float invA[4], invB[4];
    #pragma unroll
    for (int mt = 0; mt < 4; mt++) {
        float sA = 0.f, sB = 0.f;
        #pragma unroll
        for (int nt = 0; nt < 6; nt++) {
            S[mt][nt][0] = __expf(S[mt][nt][0]);
            S[mt][nt][1] = __expf(S[mt][nt][1]);
            S[mt][nt][2] = __expf(S[mt][nt][2]);
            S[mt][nt][3] = __expf(S[mt][nt][3]);
            sA += S[mt][nt][0] + S[mt][nt][1];
            sB += S[mt][nt][2] + S[mt][nt][3];
        }
        sA += __shfl_xor_sync(0xFFFFFFFFu, sA, 1);
        sA += __shfl_xor_sync(0xFFFFFFFFu, sA, 2);
        sB += __shfl_xor_sync(0xFFFFFFFFu, sB, 1);
        sB += __shfl_xor_sync(0xFFFFFFFFu, sB, 2);
        invA[mt] = 1.f / sA;
        invB[mt] = 1.f / sB;
    }

    // ================= PV: M=64 N=32 K=48 =================
    float O[4][4][4] = {};
    #pragma unroll
    for (int jg = 0; jg < 3; jg++) {
        uint32_t P[4][4];
        #pragma unroll
        for (int mt = 0; mt < 4; mt++) {
            P[mt][0] = h2pack(S[mt][2 * jg][0],     S[mt][2 * jg][1]);
            P[mt][1] = h2pack(S[mt][2 * jg][2],     S[mt][2 * jg][3]);
            P[mt][2] = h2pack(S[mt][2 * jg + 1][0], S[mt][2 * jg + 1][1]);
            P[mt][3] = h2pack(S[mt][2 * jg + 1][2], S[mt][2 * jg + 1][3]);
        }
        uint32_t V[2][4];
        const uint32_t vo = (uint32_t)((jg * 16 + (lane & 7) + ((lane >> 3) & 1) * 8) * ARS
                                       + (lane >> 4) * 16);
        #pragma unroll
        for (int dg = 0; dg < 2; dg++)
            ldsm4t(V[dg], vc + vo + dg * 32);
        #pragma unroll
        for (int mt = 0; mt < 4; mt++)
            #pragma unroll
            for (int dg = 0; dg < 2; dg++) {
                mma16816h(O[mt][dg * 2],     P[mt], V[dg][0], V[dg][1]);
                mma16816h(O[mt][dg * 2 + 1], P[mt], V[dg][2], V[dg][3]);
            }
    }

    // ================= normalize + out via smem restage (144B rows) =================
    __syncwarp();
    #pragma unroll
    for (int mt = 0; mt < 4; mt++)
        #pragma unroll
        for (int nt = 0; nt < 4; nt++) {
            const int cc = nt * 8 + c2;
            *(float2*)(wbp + (mt * 16 + r) * 144 + cc * 4) =
                make_float2(O[mt][nt][0] * invA[mt], O[mt][nt][1] * invA[mt]);
            *(float2*)(wbp + (mt * 16 + r + 8) * 144 + cc * 4) =
                make_float2(O[mt][nt][2] * invB[mt], O[mt][nt][3] * invB[mt]);
        }
    __syncwarp();
    #pragma unroll
    for (int rr = 0; rr < 2; rr++) {
        const int r2 = lane + rr * 32;
        float v[32];
        #pragma unroll
        for (int i = 0; i < 8; i++)
            *(float4*)(v + i * 4) = *(const float4*)(wbp + r2 * 144 + i * 16);
        uint32_t hw[16];
        #pragma unroll
        for (int i = 0; i < 16; i++)
            hw[i] = h2pack(v[2 * i], v[2 * i + 1]);
        const size_t off = ((size_t)(w * NW + r2)) * CDIM + h * HD;
        #pragma unroll
        for (int i = 0; i < 4; i++)
            *(uint4*)(g_ao + off + i * 8) = *(uint4*)(hw + i * 4);
    }
}

// =================================================================================
extern "C" void kernel_launch(void* const* d_in, const int* in_sizes, int n_in,
                              void* d_out, int out_size)
{
    (void)in_sizes; (void)n_in; (void)out_size;
    const float* x     = (const float*)d_in[0];
    const float* Wqkv  = (const float*)d_in[1];
    const float* bqkv  = (const float*)d_in[2];
    const float* E_k   = (const float*)d_in[3];
    const float* E_v   = (const float*)d_in[4];
    const float* kbank = (const float*)d_in[5];
    const float* vbank = (const float*)d_in[6];
    const float* Wp    = (const float*)d_in[7];
    const float* bp    = (const float*)d_in[8];
    float* out = (float*)d_out;

    cudaFuncSetAttribute(hmma_gemm<0>,
                         cudaFuncAttributeMaxDynamicSharedMemorySize, SMEMB);
    cudaFuncSetAttribute(hmma_gemm<1>,
                         cudaFuncAttributeMaxDynamicSharedMemorySize, SMEMB);
    cudaFuncSetAttribute(attn_kernel,
                         cudaFuncAttributeMaxDynamicSharedMemorySize, ATTN_SM);

    conv_x<<<8192, 256>>>(x);
    conv_w<<<1024, 64>>>(Wqkv, Wp);
    conv_eT<<<16, 128>>>(E_k, E_v);
    hmma_gemm<0><<<dim3(6, 512), 256, SMEMB>>>(bqkv, nullptr);
    attn_kernel<<<BW * 4, 64, ATTN_SM>>>(kbank, vbank);
    hmma_gemm<1><<<dim3(2, 512), 256, SMEMB>>>(bp, out);
}

// round 16
// speedup vs baseline: 2.2161x; 1.0141x over previous
#include <cuda_runtime.h>
#include <cuda_bf16.h>
#include <cuda_fp16.h>
#include <cstdint>

// ---------------- problem constants ----------------
#define NTOK    4096
#define CDIM    256
#define NH      8
#define HD      32
#define LK      32
#define GB      16
#define NW      64
#define BW      1024
#define MROWS   65536
#define NKEY    48

typedef unsigned long long u64;
typedef __half fp16;

// ---------------- device-global scratch ----------------
__device__ __align__(16) fp16  g_q[(size_t)BW * NH * NW * HD];
__device__ __align__(16) fp16  g_k[(size_t)BW * NH * NW * HD];
__device__ __align__(16) fp16  g_v[(size_t)BW * NH * NW * HD];
__device__ __align__(16) fp16  g_ao[(size_t)MROWS * CDIM];
__device__ __align__(16) fp16  g_wqkvT[768 * 256];
__device__ __align__(16) fp16  g_wpT[256 * 256];
__device__ __align__(16) fp16  g_ekT[LK * NW];
__device__ __align__(16) fp16  g_evT[LK * NW];

// ---------------- helpers ----------------
__device__ __forceinline__ uint32_t smem_u32(const void* p) {
    uint32_t a;
    asm("{ .reg .u64 t; cvta.to.shared.u64 t, %1; cvt.u32.u64 %0, t; }" : "=r"(a) : "l"(p));
    return a;
}
__device__ __forceinline__ void cp16(uint32_t saddr, const void* gaddr) {
    asm volatile("cp.async.cg.shared.global [%0], [%1], 16;"
                 :: "r"(saddr), "l"(gaddr));
}
#define CP_COMMIT() asm volatile("cp.async.commit_group;" ::: "memory")
#define CP_WAIT(n)  asm volatile("cp.async.wait_group %0;" :: "n"(n) : "memory")

__device__ __forceinline__ void ldsm4(uint32_t (&r)[4], uint32_t addr) {
    asm volatile("ldmatrix.sync.aligned.m8n8.x4.shared.b16 {%0,%1,%2,%3}, [%4];"
                 : "=r"(r[0]), "=r"(r[1]), "=r"(r[2]), "=r"(r[3]) : "r"(addr));
}
__device__ __forceinline__ void ldsm4t(uint32_t (&r)[4], uint32_t addr) {
    asm volatile("ldmatrix.sync.aligned.m8n8.x4.trans.shared.b16 {%0,%1,%2,%3}, [%4];"
                 : "=r"(r[0]), "=r"(r[1]), "=r"(r[2]), "=r"(r[3]) : "r"(addr));
}
__device__ __forceinline__ void mma16816h(float (&d)[4], const uint32_t (&a)[4],
                                          uint32_t b0, uint32_t b1) {
    asm volatile("mma.sync.aligned.m16n8k16.row.col.f32.f16.f16.f32 "
                 "{%0,%1,%2,%3}, {%4,%5,%6,%7}, {%8,%9}, {%0,%1,%2,%3};"
                 : "+f"(d[0]), "+f"(d[1]), "+f"(d[2]), "+f"(d[3])
                 : "r"(a[0]), "r"(a[1]), "r"(a[2]), "r"(a[3]), "r"(b0), "r"(b1));
}
__device__ __forceinline__ uint32_t h2pack(float x, float y) {
    __half2 h = __floats2half2_rn(x, y);
    return *(uint32_t*)&h;
}

// =================================================================================
// conv_w: W_qkv/W_proj -> [n][k] fp16 transposed, plus E_k/E_v -> E^T fp16.
//   grid 1040: blocks 0..1023 weights, 1024..1039 E^T
// =================================================================================
__global__ void __launch_bounds__(64) conv_w(const float* __restrict__ Wqkv,
                                             const float* __restrict__ Wp,
                                             const float* __restrict__ Ek,
                                             const float* __restrict__ Ev)
{
    const int blk = blockIdx.x;
    if (blk < 1024) {
        const int n = blk;
        for (int k = threadIdx.x; k < CDIM; k += 64) {
            if (n < 768)
                g_wqkvT[(size_t)n * CDIM + k] = __float2half_rn(Wqkv[(size_t)k * 768 + n]);
            else
                g_wpT[(size_t)(n - 768) * CDIM + k] = __float2half_rn(Wp[(size_t)k * CDIM + (n - 768)]);
        }
    } else {
        const int base = (blk - 1024) * 128 + threadIdx.x * 2;   // 0..2046 step
        #pragma unroll
        for (int u = 0; u < 2; u++) {
            const int t = base + u;
            const int l = t >> 6, n = t & 63;
            g_ekT[t] = __float2half_rn(Ek[n * LK + l]);
            g_evT[t] = __float2half_rn(Ev[n * LK + l]);
        }
    }
}

// =================================================================================
// HMMA fp16 GEMM, single fp16 A/B -> 1 mma per tile. ONE sync per k-iteration.
//   BM=128 BN=128 BK=32, 256 thr, warp tile 64x32 (2m x 4n), 2-stage.
//   MODE 0: qkv — A read DIRECTLY from fp32 x (window gather) via LDG+cvt+STS
//           (conv_x pass eliminated); writes q/k/v fp16 (q pre-scaled).
//   MODE 1: proj — A = g_ao via cp.async; window-reverse fp32 out + bias.
// =================================================================================
#define RS   80
#define AA   0
#define BB   10240
#define STG  20480
#define SMEMB (2 * STG)

template<int MODE>
__global__ void __launch_bounds__(256) hmma_gemm(const float* __restrict__ xin,
                                                 const float* __restrict__ bias,
                                                 float* __restrict__ outp)
{
    extern __shared__ char sm[];
    const uint32_t smb = smem_u32(sm);
    const int tid  = threadIdx.x;
    const int lane = tid & 31, wid = tid >> 5;
    const int warp_m = wid >> 2, warp_n = wid & 3;      // 2m x 4n
    const int bx = blockIdx.y;          // M-tile
    const int by = blockIdx.x;          // N-tile (fast axis -> A/L2 reuse)

    const fp16* B_g = (MODE == 0) ? g_wqkvT : g_wpT;
    const size_t b_base = (size_t)(by * 128) * CDIM;

    // ---- A chunk ids: 2 chunks/thread; chunk c -> idx = tid + c*256,
    //      row = idx>>2 (0..127), kc = idx&3 (8 fp16 each)
    const float* xrow[2];               // MODE 0: gathered fp32 row base
    const fp16*  arow[2];               // MODE 1
    #pragma unroll
    for (int c = 0; c < 2; c++) {
        const int idx = tid + c * 256;
        const int row = idx >> 2;
        const int kc  = idx & 3;
        if (MODE == 0) {
            const int r_in = bx * 128 + row;
            const int w_in = r_in >> 6, t_in = r_in & 63;
            const int b    = w_in >> 6, wrem = w_in & 63;
            const int gtok = (((wrem >> 3) * 8 + (t_in >> 3)) << 6)
                           + ((wrem & 7) * 8 + (t_in & 7));
            xrow[c] = xin + ((size_t)(b * NTOK + gtok)) * CDIM + kc * 8;
        } else {
            arow[c] = g_ao + (size_t)(bx * 128 + row) * CDIM + kc * 8;
        }
    }

    uint32_t areg[2][4];
    auto ldgA = [&](int kt) {
        #pragma unroll
        for (int c = 0; c < 2; c++) {
            float4 v0 = *(const float4*)(xrow[c] + kt * 32);
            float4 v1 = *(const float4*)(xrow[c] + kt * 32 + 4);
            areg[c][0] = h2pack(v0.x, v0.y);
            areg[c][1] = h2pack(v0.z, v0.w);
            areg[c][2] = h2pack(v1.x, v1.y);
            areg[c][3] = h2pack(v1.z, v1.w);
        }
    };
    auto stsA = [&](int s) {
        #pragma unroll
        for (int c = 0; c < 2; c++) {
            const int idx = tid + c * 256;
            const int row = idx >> 2, kc = idx & 3;
            *(uint4*)(sm + s * STG + AA + row * RS + kc * 16) = *(uint4*)areg[c];
        }
    };
    auto loadB = [&](int s, int kt) {
        #pragma unroll
        for (int c = 0; c < 2; c++) {
            const int idx = tid + c * 256;
            const int row = idx >> 2, kc = idx & 3;
            cp16(smb + s * STG + BB + row * RS + kc * 16,
                 B_g + b_base + (size_t)row * CDIM + (size_t)kt * 32 + kc * 8);
        }
    };
    auto loadA_cp = [&](int s, int kt) {
        #pragma unroll
        for (int c = 0; c < 2; c++) {
            const int idx = tid + c * 256;
            const int row = idx >> 2, kc = idx & 3;
            cp16(smb + s * STG + AA + row * RS + kc * 16,
                 arow[c] + (size_t)kt * 32);
        }
    };

    const uint32_t a_frag = (uint32_t)((warp_m * 64 + (lane & 15)) * RS
                                       + (lane >> 4) * 16);
    const uint32_t b_frag = (uint32_t)((warp_n * 32 + (lane & 7) + ((lane >> 4) << 3)) * RS
                                       + ((lane >> 3) & 1) * 16);

    float acc[4][4][4] = {};

    // ---- prologue
    if (MODE == 0) ldgA(0);
    else           loadA_cp(0, 0);
    loadB(0, 0);
    CP_COMMIT();

    #pragma unroll 1
    for (int it = 0; it < 8; it++) {
        CP_WAIT(0);
        if (MODE == 0) stsA(it & 1);
        __syncthreads();
        if (it < 7) {
            if (MODE == 0) ldgA(it + 1);
            else           loadA_cp((it + 1) & 1, it + 1);
            loadB((it + 1) & 1, it + 1);
            CP_COMMIT();
        }

        const uint32_t st = smb + (it & 1) * STG;
        #pragma unroll
        for (int kk = 0; kk < 2; kk++) {
            uint32_t aa[4][4], bb[4][2];
            #pragma unroll
            for (int mt = 0; mt < 4; mt++)
                ldsm4(aa[mt], st + AA + a_frag + mt * (16 * RS) + kk * 32);
            #pragma unroll
            for (int np = 0; np < 2; np++) {
                uint32_t tb[4];
                ldsm4(tb, st + BB + b_frag + np * (16 * RS) + kk * 32);
                bb[np * 2][0] = tb[0]; bb[np * 2][1] = tb[1];
                bb[np * 2 + 1][0] = tb[2]; bb[np * 2 + 1][1] = tb[3];
            }
            #pragma unroll
            for (int mt = 0; mt < 4; mt++)
                #pragma unroll
                for (int nt = 0; nt < 4; nt++)
                    mma16816h(acc[mt][nt], aa[mt], bb[nt][0], bb[nt][1]);
        }
    }

    // ---------------- epilogue ----------------
    const int w = bx * 2 + warp_m;
    const int qrow = lane >> 2;
    const int qcol = (lane & 3) * 2;

    if (MODE == 0) {
        const int s  = by >> 1;                       // 0=q,1=k,2=v
        fp16* dst = (s == 0) ? g_q : ((s == 1) ? g_k : g_v);
        const float qs = (s == 0) ? 0.17677669529663687f : 1.0f;
        const int h = (by & 1) * 4 + warp_n;
        const size_t hb = ((size_t)(w * NH + h)) << 11;
        #pragma unroll
        for (int nt = 0; nt < 4; nt++) {
            const int d  = nt * 8 + qcol;
            const int jg = by * 128 + warp_n * 32 + d;
            const float2 b2 = *(const float2*)(bias + jg);
            #pragma unroll
            for (int mt = 0; mt < 4; mt++) {
                const int tok = mt * 16 + qrow;
                *(uint32_t*)(dst + hb + ((size_t)tok << 5) + d) =
                    h2pack((acc[mt][nt][0] + b2.x) * qs, (acc[mt][nt][1] + b2.y) * qs);
                *(uint32_t*)(dst + hb + ((size_t)(tok + 8) << 5) + d) =
                    h2pack((acc[mt][nt][2] + b2.x) * qs, (acc[mt][nt][3] + b2.y) * qs);
            }
        }
    } else {
        const int b = w >> 6, wrem = w & 63;
        #pragma unroll
        for (int nt = 0; nt < 4; nt++) {
            const int jg = by * 128 + warp_n * 32 + nt * 8 + qcol;
            const float2 b2 = *(const float2*)(bias + jg);
            #pragma unroll
            for (int mt = 0; mt < 4; mt++) {
                #pragma unroll
                for (int half = 0; half < 2; half++) {
                    const int tok = mt * 16 + qrow + half * 8;
                    const int gtok = (((wrem >> 3) * 8 + (tok >> 3)) << 6)
                                   + ((wrem & 7) * 8 + (tok & 7));
                    float2 o = make_float2(acc[mt][nt][half * 2]     + b2.x,
                                           acc[mt][nt][half * 2 + 1] + b2.y);
                    *(float2*)(outp + ((size_t)(b * NTOK + gtok)) * CDIM + jg) = o;
                }
            }
        }
    }
}

// =================================================================================
// HMMA attention, all single fp16 (1 mma per tile).
//   Block = (window, 2 heads), 64 threads, warp = head. 80B row strides.
// =================================================================================
#define ET_SZ   4608
#define ARS     80
#define W_STG   0
#define W_KC    5120
#define W_VC    8960
#define W_SZ    12800
#define ATTN_SM (2 * ET_SZ + 2 * W_SZ)   // 34816

__global__ void __launch_bounds__(64) attn_kernel(const float* __restrict__ k_bank,
                                                  const float* __restrict__ v_bank)
{
    extern __shared__ char sm[];
    const uint32_t smb = smem_u32(sm);
    const int tid  = threadIdx.x;
    const int lane = tid & 31, wid = tid >> 5;
    const int blk  = blockIdx.x;
    const int w    = blk >> 2;
    const int h    = (blk & 3) * 2 + wid;

    // ---- stage E^T matrices (block cooperative): 2 mats x 256 uint4
    {
        const fp16* srcs[2] = { g_ekT, g_evT };
        #pragma unroll
        for (int i = 0; i < 8; i++) {
            const int idx = tid + i * 64;
            const int mat = idx >> 8;
            const int r   = (idx & 255) >> 3;
            const int c   = idx & 7;
            *(uint4*)(sm + mat * ET_SZ + r * 144 + c * 16) =
                *(const uint4*)(srcs[mat] + r * 64 + c * 8);
        }
    }
    __syncthreads();

    char* wbp = sm + 2 * ET_SZ + wid * W_SZ;
    const uint32_t wbu = smb + 2 * ET_SZ + wid * W_SZ;
    const uint32_t stg = wbu + W_STG;
    const uint32_t kc  = wbu + W_KC;
    const uint32_t vc  = wbu + W_VC;

    const size_t qkvoff = ((size_t)(w * NH + h)) << 11;
    const int r  = lane >> 2;
    const int c2 = (lane & 3) * 2;

    // ================= compression: K then V =================
    #pragma unroll 1
    for (int sel = 0; sel < 2; sel++) {
        const fp16* src = sel ? g_v : g_k;
        const float* bank = sel ? v_bank : k_bank;
        char* ccp = wbp + (sel ? W_VC : W_KC);
        const uint32_t eT = smb + (sel ? ET_SZ : 0);

        #pragma unroll
        for (int i = 0; i < 8; i++) {
            const int idx = lane + i * 32;
            const int rr = idx >> 2, cc = idx & 3;
            *(uint4*)(wbp + W_STG + rr * ARS + cc * 16) =
                *(const uint4*)(src + qkvoff + idx * 8);
        }
        {
            const int g  = lane >> 1;
            const int d0 = (lane & 1) * 16;
            float bv[16];
            #pragma unroll
            for (int i = 0; i < 4; i++)
                *(float4*)(bv + i * 4) =
                    *(const float4*)(bank + g * CDIM + h * HD + d0 + i * 4);
            #pragma unroll
            for (int i = 0; i < 8; i++)
                *(uint32_t*)(ccp + (32 + g) * ARS + (d0 + 2 * i) * 2) =
                    h2pack(bv[2 * i], bv[2 * i + 1]);
        }
        __syncwarp();

        float acc[2][4][4] = {};
        #pragma unroll
        for (int kt = 0; kt < 4; kt++) {
            uint32_t A[2][4], B[2][4];
            #pragma unroll
            for (int mt = 0; mt < 2; mt++) {
                const uint32_t ao = (uint32_t)((mt * 16 + (lane & 15)) * 144
                                               + kt * 32 + (lane >> 4) * 16);
                ldsm4(A[mt], eT + ao);
            }
            const uint32_t to = (uint32_t)((kt * 16 + (lane & 7) + ((lane >> 3) & 1) * 8) * ARS
                                           + (lane >> 4) * 16);
            #pragma unroll
            for (int dg = 0; dg < 2; dg++)
                ldsm4t(B[dg], stg + to + dg * 32);
            #pragma unroll
            for (int mt = 0; mt < 2; mt++)
                #pragma unroll
                for (int dg = 0; dg < 2; dg++) {
                    mma16816h(acc[mt][dg * 2],     A[mt], B[dg][0], B[dg][1]);
                    mma16816h(acc[mt][dg * 2 + 1], A[mt], B[dg][2], B[dg][3]);
                }
        }
        #pragma unroll
        for (int mt = 0; mt < 2; mt++)
            #pragma unroll
            for (int nt = 0; nt < 4; nt++) {
                const int d = nt * 8 + c2;
                *(uint32_t*)(ccp + (mt * 16 + r) * ARS + d * 2) =
                    h2pack(acc[mt][nt][0], acc[mt][nt][1]);
                *(uint32_t*)(ccp + (mt * 16 + r + 8) * ARS + d * 2) =
                    h2pack(acc[mt][nt][2], acc[mt][nt][3]);
            }
        __syncwarp();
    }

    // ================= stage Q (pre-scaled in qkv epilogue) =================
    #pragma unroll
    for (int i = 0; i < 8; i++) {
        const int idx = lane + i * 32;
        const int rr = idx >> 2, cc = idx & 3;
        *(uint4*)(wbp + W_STG + rr * ARS + cc * 16) =
            *(const uint4*)(g_q + qkvoff + idx * 8);
    }
    __syncwarp();

    // ================= QK: M=64 N=48 K=32 =================
    float S[4][6][4] = {};
    #pragma unroll
    for (int kd = 0; kd < 2; kd++) {
        uint32_t Q[4][4], K[3][4];
        #pragma unroll
        for (int mt = 0; mt < 4; mt++) {
            const uint32_t ao = (uint32_t)((mt * 16 + (lane & 15)) * ARS
                                           + kd * 32 + (lane >> 4) * 16);
            ldsm4(Q[mt], stg + ao);
        }
        const uint32_t bo = (uint32_t)(((lane & 7) + ((lane >> 4) << 3)) * ARS
                                       + ((lane >> 3) & 1) * 16 + kd * 32);
        #pragma unroll
        for (int jg = 0; jg < 3; jg++)
            ldsm4(K[jg], kc + jg * (16 * ARS) + bo);
        #pragma unroll
        for (int mt = 0; mt < 4; mt++)
            #pragma unroll
            for (int jg = 0; jg < 3; jg++) {
                mma16816h(S[mt][jg * 2],     Q[mt], K[jg][0], K[jg][1]);
                mma16816h(S[mt][jg * 2 + 1], Q[mt], K[jg][2], K[jg][3]);
            }
    }

    // ================= softmax =================
    float invA[4], invB[4];
    #pragma unroll
    for (int mt = 0; mt < 4; mt++) {
        float sA = 0.f, sB = 0.f;
        #pragma unroll
        for (int nt = 0; nt < 6; nt++) {
            S[mt][nt][0] = __expf(S[mt][nt][0]);
            S[mt][nt][1] = __expf(S[mt][nt][1]);
            S[mt][nt][2] = __expf(S[mt][nt][2]);
            S[mt][nt][3] = __expf(S[mt][nt][3]);
            sA += S[mt][nt][0] + S[mt][nt][1];
            sB += S[mt][nt][2] + S[mt][nt][3];
        }
        sA += __shfl_xor_sync(0xFFFFFFFFu, sA, 1);
        sA += __shfl_xor_sync(0xFFFFFFFFu, sA, 2);
        sB += __shfl_xor_sync(0xFFFFFFFFu, sB, 1);
        sB += __shfl_xor_sync(0xFFFFFFFFu, sB, 2);
        invA[mt] = 1.f / sA;
        invB[mt] = 1.f / sB;
    }

    // ================= PV: M=64 N=32 K=48 =================
    float O[4][4][4] = {};
    #pragma unroll
    for (int jg = 0; jg < 3; jg++) {
        uint32_t P[4][4];
        #pragma unroll
        for (int mt = 0; mt < 4; mt++) {
            P[mt][0] = h2pack(S[mt][2 * jg][0],     S[mt][2 * jg][1]);
            P[mt][1] = h2pack(S[mt][2 * jg][2],     S[mt][2 * jg][3]);
            P[mt][2] = h2pack(S[mt][2 * jg + 1][0], S[mt][2 * jg + 1][1]);
            P[mt][3] = h2pack(S[mt][2 * jg + 1][2], S[mt][2 * jg + 1][3]);
        }
        uint32_t V[2][4];
        const uint32_t vo = (uint32_t)((jg * 16 + (lane & 7) + ((lane >> 3) & 1) * 8) * ARS
                                       + (lane >> 4) * 16);
        #pragma unroll
        for (int dg = 0; dg < 2; dg++)
            ldsm4t(V[dg], vc + vo + dg * 32);
        #pragma unroll
        for (int mt = 0; mt < 4; mt++)
            #pragma unroll
            for (int dg = 0; dg < 2; dg++) {
                mma16816h(O[mt][dg * 2],     P[mt], V[dg][0], V[dg][1]);
                mma16816h(O[mt][dg * 2 + 1], P[mt], V[dg][2], V[dg][3]);
            }
    }

    // ================= normalize + out via smem restage (144B rows) =================
    __syncwarp();
    #pragma unroll
    for (int mt = 0; mt < 4; mt++)
        #pragma unroll
        for (int nt = 0; nt < 4; nt++) {
            const int cc = nt * 8 + c2;
            *(float2*)(wbp + (mt * 16 + r) * 144 + cc * 4) =
                make_float2(O[mt][nt][0] * invA[mt], O[mt][nt][1] * invA[mt]);
            *(float2*)(wbp + (mt * 16 + r + 8) * 144 + cc * 4) =
                make_float2(O[mt][nt][2] * invB[mt], O[mt][nt][3] * invB[mt]);
        }
    __syncwarp();
    #pragma unroll
    for (int rr = 0; rr < 2; rr++) {
        const int r2 = lane + rr * 32;
        float v[32];
        #pragma unroll
        for (int i = 0; i < 8; i++)
            *(float4*)(v + i * 4) = *(const float4*)(wbp + r2 * 144 + i * 16);
        uint32_t hw[16];
        #pragma unroll
        for (int i = 0; i < 16; i++)
            hw[i] = h2pack(v[2 * i], v[2 * i + 1]);
        const size_t off = ((size_t)(w * NW + r2)) * CDIM + h * HD;
        #pragma unroll
        for (int i = 0; i < 4; i++)
            *(uint4*)(g_ao + off + i * 8) = *(uint4*)(hw + i * 4);
    }
}

// =================================================================================
extern "C" void kernel_launch(void* const* d_in, const int* in_sizes, int n_in,
                              void* d_out, int out_size)
{
    (void)in_sizes; (void)n_in; (void)out_size;
    const float* x     = (const float*)d_in[0];
    const float* Wqkv  = (const float*)d_in[1];
    const float* bqkv  = (const float*)d_in[2];
    const float* E_k   = (const float*)d_in[3];
    const float* E_v   = (const float*)d_in[4];
    const float* kbank = (const float*)d_in[5];
    const float* vbank = (const float*)d_in[6];
    const float* Wp    = (const float*)d_in[7];
    const float* bp    = (const float*)d_in[8];
    float* out = (float*)d_out;

    cudaFuncSetAttribute(hmma_gemm<0>,
                         cudaFuncAttributeMaxDynamicSharedMemorySize, SMEMB);
    cudaFuncSetAttribute(hmma_gemm<1>,
                         cudaFuncAttributeMaxDynamicSharedMemorySize, SMEMB);
    cudaFuncSetAttribute(attn_kernel,
                         cudaFuncAttributeMaxDynamicSharedMemorySize, ATTN_SM);

    conv_w<<<1040, 64>>>(Wqkv, Wp, E_k, E_v);
    hmma_gemm<0><<<dim3(6, 512), 256, SMEMB>>>(x, bqkv, nullptr);
    attn_kernel<<<BW * 4, 64, ATTN_SM>>>(kbank, vbank);
    hmma_gemm<1><<<dim3(2, 512), 256, SMEMB>>>(nullptr, bp, out);
}